// round 7
// baseline (speedup 1.0000x reference)
#include <cuda_runtime.h>
#include <cuda_bf16.h>
#include <cstdint>

#define NN   50000
#define EE   500000
#define DD   256
#define KTOT 768            // 3 * DD
#define MPAD 50048          // 391 * 128
#define NSEG3 (3 * NN)

#define MB_H0   196         // M-blocks in half 0
#define ROWS_H0 (MB_H0 * 128)          // 25088
#define ROWS_H1 (NN - ROWS_H0)         // 24912
#define NGATHER 148                    // gather blocks inside mixed kernel
#define NMIXED  (MB_H0 + NGATHER)      // 344

// ---------------- scratch (static device globals; zero-initialized at load) ----------------
__device__ int            g_is64;
__device__ int            g_icnt[NSEG3];
__device__ int            g_cur[NSEG3];
__device__ int            g_off[NSEG3];
__device__ int            g_bsum[1024];
__device__ int            g_bsumx[1024];
__device__ int            g_csr[3 * EE];
__device__ float          g_flg[NSEG3];
__device__ unsigned short g_ah[(size_t)MPAD * KTOT];
__device__ unsigned short g_al[(size_t)MPAD * KTOT];
__device__ unsigned short g_bh[(size_t)DD * KTOT];
__device__ unsigned short g_bl[(size_t)DD * KTOT];

// ================= helpers =================
__device__ __forceinline__ uint32_t smem_u32(const void* p) {
    uint32_t a;
    asm("{ .reg .u64 t; cvta.to.shared.u64 t, %1; cvt.u32.u64 %0, t; }" : "=r"(a) : "l"(p));
    return a;
}
__device__ __forceinline__ uint32_t sw128(uint32_t b) { return b ^ ((b >> 3) & 0x70); }

__device__ __forceinline__ void cp16(uint32_t dst, const void* src) {
    asm volatile("cp.async.cg.shared.global [%0], [%1], 16;" :: "r"(dst), "l"(src));
}
__device__ __forceinline__ void ldm4(uint32_t* r, uint32_t addr) {
    asm volatile("ldmatrix.sync.aligned.m8n8.x4.shared.b16 {%0,%1,%2,%3}, [%4];"
                 : "=r"(r[0]), "=r"(r[1]), "=r"(r[2]), "=r"(r[3]) : "r"(addr));
}
__device__ __forceinline__ void mma_bf16(float* c, const uint32_t* a, const uint32_t* b) {
    asm volatile("mma.sync.aligned.m16n8k16.row.col.f32.bf16.bf16.f32 "
                 "{%0,%1,%2,%3}, {%4,%5,%6,%7}, {%8,%9}, {%0,%1,%2,%3};"
                 : "+f"(c[0]), "+f"(c[1]), "+f"(c[2]), "+f"(c[3])
                 : "r"(a[0]), "r"(a[1]), "r"(a[2]), "r"(a[3]), "r"(b[0]), "r"(b[1]));
}
__device__ __forceinline__ void bsplit(float a, unsigned short& h, unsigned short& l) {
    __nv_bfloat16 hb = __float2bfloat16_rn(a);
    float hf = __bfloat162float(hb);
    __nv_bfloat16 lb = __float2bfloat16_rn(a - hf);
    h = *reinterpret_cast<unsigned short*>(&hb);
    l = *reinterpret_cast<unsigned short*>(&lb);
}

// ================= phase 0: detect + zero counters (merged) =================
__global__ void zero_detect_kernel(const int* __restrict__ src) {
    int i = blockIdx.x * blockDim.x + threadIdx.x;
    if (i < NSEG3) { g_icnt[i] = 0; g_cur[i] = 0; }
    if (i == 0) {
        int ok = 1;
#pragma unroll
        for (int k = 0; k < 32; k++)
            if (src[2 * k + 1] != 0) ok = 0;
        g_is64 = ok;
    }
}

// ================= phase 1: CSR build =================
__global__ __launch_bounds__(256) void hist_kernel(
    const void* __restrict__ dst0, const void* __restrict__ dst1,
    const void* __restrict__ dst2)
{
    int e = blockIdx.x * blockDim.x + threadIdx.x;
    if (e >= EE) return;
    const int seg = blockIdx.z;
    const void* dst = (seg == 0) ? dst0 : ((seg == 1) ? dst1 : dst2);
    int d = g_is64 ? (int)((const long long*)dst)[e] : ((const int*)dst)[e];
    if ((unsigned)d >= NN) return;
    atomicAdd(&g_icnt[seg * NN + d], 1);
}

__global__ __launch_bounds__(256) void scan1_kernel() {
    __shared__ int sh[256];
    int t = threadIdx.x;
    int i = blockIdx.x * 256 + t;
    int v = (i < NSEG3) ? g_icnt[i] : 0;
    sh[t] = v;
    __syncthreads();
    int acc = v;
#pragma unroll
    for (int ofs = 1; ofs < 256; ofs <<= 1) {
        int o = (t >= ofs) ? sh[t - ofs] : 0;
        __syncthreads();
        acc += o;
        sh[t] = acc;
        __syncthreads();
    }
    if (i < NSEG3) g_off[i] = acc - v;
    if (t == 255) g_bsum[blockIdx.x] = acc;
}

__global__ __launch_bounds__(1024) void scan2_kernel(int nblocks) {
    __shared__ int sh[1024];
    int t = threadIdx.x;
    int v = (t < nblocks) ? g_bsum[t] : 0;
    sh[t] = v;
    __syncthreads();
    int acc = v;
#pragma unroll
    for (int ofs = 1; ofs < 1024; ofs <<= 1) {
        int o = (t >= ofs) ? sh[t - ofs] : 0;
        __syncthreads();
        acc += o;
        sh[t] = acc;
        __syncthreads();
    }
    g_bsumx[t] = acc - v;
}

__global__ __launch_bounds__(256) void scatter_kernel(
    const void* __restrict__ src0, const void* __restrict__ dst0,
    const void* __restrict__ src1, const void* __restrict__ dst1,
    const void* __restrict__ src2, const void* __restrict__ dst2)
{
    int e = blockIdx.x * blockDim.x + threadIdx.x;
    if (e >= EE) return;
    const int seg = blockIdx.z;
    const void* src = (seg == 0) ? src0 : ((seg == 1) ? src1 : src2);
    const void* dst = (seg == 0) ? dst0 : ((seg == 1) ? dst1 : dst2);
    int s, d;
    if (g_is64) {
        s = (int)((const long long*)src)[e];
        d = (int)((const long long*)dst)[e];
    } else {
        s = ((const int*)src)[e];
        d = ((const int*)dst)[e];
    }
    if ((unsigned)s >= NN || (unsigned)d >= NN) return;
    int idx  = seg * NN + d;
    int base = g_off[idx] + g_bsumx[idx >> 8];
    int pos  = base + atomicAdd(&g_cur[idx], 1);
    g_csr[pos] = s;
}

// ================= gather core: one warp per (seg,node) task =================
__device__ __forceinline__ void gather_one(int seg, int node, int lane,
                                           const float* __restrict__ feat)
{
    const int gw   = seg * NN + node;
    const int deg  = g_icnt[gw];
    const int base = g_off[gw] + g_bsumx[gw >> 8];

    float4 a0 = make_float4(0.f, 0.f, 0.f, 0.f);
    float4 a1 = make_float4(0.f, 0.f, 0.f, 0.f);

    int p = 0;
    for (; p + 1 < deg; p += 2) {
        int s0 = g_csr[base + p];
        int s1 = g_csr[base + p + 1];
        const float4* f0 = reinterpret_cast<const float4*>(feat + (size_t)s0 * DD);
        const float4* f1 = reinterpret_cast<const float4*>(feat + (size_t)s1 * DD);
        float4 u0 = __ldg(&f0[lane]);
        float4 u1 = __ldg(&f0[lane + 32]);
        float4 v0 = __ldg(&f1[lane]);
        float4 v1 = __ldg(&f1[lane + 32]);
        a0.x += u0.x + v0.x; a0.y += u0.y + v0.y; a0.z += u0.z + v0.z; a0.w += u0.w + v0.w;
        a1.x += u1.x + v1.x; a1.y += u1.y + v1.y; a1.z += u1.z + v1.z; a1.w += u1.w + v1.w;
    }
    if (p < deg) {
        int s0 = g_csr[base + p];
        const float4* f0 = reinterpret_cast<const float4*>(feat + (size_t)s0 * DD);
        float4 u0 = __ldg(&f0[lane]);
        float4 u1 = __ldg(&f0[lane + 32]);
        a0.x += u0.x; a0.y += u0.y; a0.z += u0.z; a0.w += u0.w;
        a1.x += u1.x; a1.y += u1.y; a1.z += u1.z; a1.w += u1.w;
    }

    const float inv = (deg > 0) ? (1.f / (float)deg) : 0.f;
    unsigned short h[8], l[8];
    bsplit(a0.x * inv, h[0], l[0]);
    bsplit(a0.y * inv, h[1], l[1]);
    bsplit(a0.z * inv, h[2], l[2]);
    bsplit(a0.w * inv, h[3], l[3]);
    bsplit(a1.x * inv, h[4], l[4]);
    bsplit(a1.y * inv, h[5], l[5]);
    bsplit(a1.z * inv, h[6], l[6]);
    bsplit(a1.w * inv, h[7], l[7]);

    unsigned short* rh = g_ah + (size_t)node * KTOT + seg * DD;
    unsigned short* rl = g_al + (size_t)node * KTOT + seg * DD;
    uint2 H0, H1, L0, L1;
    H0.x = (uint32_t)h[0] | ((uint32_t)h[1] << 16);
    H0.y = (uint32_t)h[2] | ((uint32_t)h[3] << 16);
    H1.x = (uint32_t)h[4] | ((uint32_t)h[5] << 16);
    H1.y = (uint32_t)h[6] | ((uint32_t)h[7] << 16);
    L0.x = (uint32_t)l[0] | ((uint32_t)l[1] << 16);
    L0.y = (uint32_t)l[2] | ((uint32_t)l[3] << 16);
    L1.x = (uint32_t)l[4] | ((uint32_t)l[5] << 16);
    L1.y = (uint32_t)l[6] | ((uint32_t)l[7] << 16);
    *reinterpret_cast<uint2*>(rh + 4 * lane)       = H0;
    *reinterpret_cast<uint2*>(rh + 128 + 4 * lane) = H1;
    *reinterpret_cast<uint2*>(rl + 4 * lane)       = L0;
    *reinterpret_cast<uint2*>(rl + 128 + 4 * lane) = L1;
    if (lane == 0)
        g_flg[gw] = (deg > 0) ? 1.f : 0.f;
}

// ================= gather half 0: rows [0, ROWS_H0) =================
__global__ __launch_bounds__(256) void gather_h0_kernel(const float* __restrict__ feat)
{
    int t = (blockIdx.x * blockDim.x + threadIdx.x) >> 5;
    const int ntasks = 3 * ROWS_H0;
    if (t >= ntasks) return;
    int seg  = t / ROWS_H0;
    int node = t - seg * ROWS_H0;
    gather_one(seg, node, threadIdx.x & 31, feat);
}

// ================= phase 2b: B transpose + split =================
__global__ void convertB_kernel(const float* __restrict__ W0,
                                const float* __restrict__ W1,
                                const float* __restrict__ W2) {
    __shared__ float tile[32][33];
    const int seg = blockIdx.z;
    const float* W = (seg == 0) ? W0 : ((seg == 1) ? W1 : W2);
    const int kb = blockIdx.x * 32, nb = blockIdx.y * 32;
    const int tx = threadIdx.x, ty = threadIdx.y;
#pragma unroll
    for (int i = 0; i < 32; i += 8)
        tile[ty + i][tx] = W[(size_t)(kb + ty + i) * DD + nb + tx];
    __syncthreads();
#pragma unroll
    for (int i = 0; i < 32; i += 8) {
        int n = nb + ty + i, k = kb + tx;
        unsigned short h, l;
        bsplit(tile[tx][ty + i], h, l);
        g_bh[(size_t)n * KTOT + seg * DD + k] = h;
        g_bl[(size_t)n * KTOT + seg * DD + k] = l;
    }
}

// ================= GEMM core (identical math to R6 pass) =================
#define O_AH 0
#define O_AL 16384
#define O_BH 32768
#define O_BL 65536
#define STG_SZ 98304
#define NCHUNK 12
#define SMEM_GEMM (2 * STG_SZ)

__device__ __forceinline__ void load_chunk(int kc, uint32_t stg, int t, int m0) {
    const char* ahg = (const char*)g_ah + ((size_t)m0 * KTOT + kc * 64) * 2;
    const char* alg = (const char*)g_al + ((size_t)m0 * KTOT + kc * 64) * 2;
    const char* bhg = (const char*)g_bh + ((size_t)kc * 64) * 2;
    const char* blg = (const char*)g_bl + ((size_t)kc * 64) * 2;
#pragma unroll
    for (int i = t; i < 1024; i += 256) {
        int r = i >> 3, j = (i & 7) * 16;
        uint32_t so = sw128(r * 128 + j);
        size_t  go = (size_t)r * (KTOT * 2) + j;
        cp16(stg + O_AH + so, ahg + go);
        cp16(stg + O_AL + so, alg + go);
    }
#pragma unroll
    for (int i = t; i < 2048; i += 256) {
        int r = i >> 3, j = (i & 7) * 16;
        uint32_t so = sw128(r * 128 + j);
        size_t  go = (size_t)r * (KTOT * 2) + j;
        cp16(stg + O_BH + so, bhg + go);
        cp16(stg + O_BL + so, blg + go);
    }
    asm volatile("cp.async.commit_group;" ::: "memory");
}

__device__ void gemm_block(int m0, const float* __restrict__ b0,
                           const float* __restrict__ b1, const float* __restrict__ b2,
                           float* __restrict__ out)
{
    extern __shared__ char smem[];
    const uint32_t sb = smem_u32(smem);
    const int t = threadIdx.x, wid = t >> 5, lane = t & 31;
    const int wm = wid & 1, wn = wid >> 1;

    float acc[4][8][4];
#pragma unroll
    for (int i = 0; i < 4; i++)
#pragma unroll
        for (int j = 0; j < 8; j++)
#pragma unroll
            for (int k = 0; k < 4; k++) acc[i][j][k] = 0.f;

    load_chunk(0, sb, t, m0);
    load_chunk(1, sb + STG_SZ, t, m0);

    const uint32_t arow  = (uint32_t)(wm * 64 + (lane & 15));
    const uint32_t acol8 = (uint32_t)(lane >> 4);
    const uint32_t brow  = (uint32_t)(wn * 64 + (lane & 7) + ((lane >> 4) & 1) * 8);
    const uint32_t bcol8 = (uint32_t)((lane >> 3) & 1);

#pragma unroll 1
    for (int c = 0; c < NCHUNK; c++) {
        const uint32_t stg = sb + (uint32_t)(c & 1) * STG_SZ;

        asm volatile("cp.async.wait_group 1;" ::: "memory");
        __syncthreads();

#pragma unroll
        for (int ks = 0; ks < 4; ks++) {
            uint32_t ah[4][4], al[4][4];
#pragma unroll
            for (int mf = 0; mf < 4; mf++) {
                uint32_t off = sw128((arow + mf * 16) * 128 + (ks * 16 + acol8 * 8) * 2);
                ldm4(ah[mf], stg + O_AH + off);
                ldm4(al[mf], stg + O_AL + off);
            }
#pragma unroll
            for (int nf2 = 0; nf2 < 4; nf2++) {
                uint32_t bh[4], bl[4];
                uint32_t off = sw128((brow + nf2 * 16) * 128 + (ks * 16 + bcol8 * 8) * 2);
                ldm4(bh, stg + O_BH + off);
                ldm4(bl, stg + O_BL + off);
#pragma unroll
                for (int mf = 0; mf < 4; mf++)
#pragma unroll
                    for (int j = 0; j < 2; j++) {
                        float* a = acc[mf][nf2 * 2 + j];
                        mma_bf16(a, ah[mf], &bh[2 * j]);
                        mma_bf16(a, ah[mf], &bl[2 * j]);
                        mma_bf16(a, al[mf], &bh[2 * j]);
                    }
            }
        }

        __syncthreads();
        if (c + 2 < NCHUNK)
            load_chunk(c + 2, sb + (uint32_t)(c & 1) * STG_SZ, t, m0);
    }

    const int gid = lane >> 2, t4 = lane & 3;
    float2 bb0[8], bb1[8], bb2[8];
#pragma unroll
    for (int nf = 0; nf < 8; nf++) {
        int col = wn * 64 + nf * 8 + t4 * 2;
        bb0[nf] = *reinterpret_cast<const float2*>(b0 + col);
        bb1[nf] = *reinterpret_cast<const float2*>(b1 + col);
        bb2[nf] = *reinterpret_cast<const float2*>(b2 + col);
    }
#pragma unroll
    for (int mf = 0; mf < 4; mf++) {
#pragma unroll
        for (int half = 0; half < 2; half++) {
            int row = m0 + wm * 64 + mf * 16 + gid + half * 8;
            if (row >= NN) continue;
            float f0 = g_flg[row], f1 = g_flg[NN + row], f2 = g_flg[2 * NN + row];
#pragma unroll
            for (int nf = 0; nf < 8; nf++) {
                int col = wn * 64 + nf * 8 + t4 * 2;
                float2 o;
                o.x = fmaxf(acc[mf][nf][2 * half]     + f0 * bb0[nf].x + f1 * bb1[nf].x + f2 * bb2[nf].x, 0.f);
                o.y = fmaxf(acc[mf][nf][2 * half + 1] + f0 * bb0[nf].y + f1 * bb1[nf].y + f2 * bb2[nf].y, 0.f);
                *reinterpret_cast<float2*>(out + (size_t)row * DD + col) = o;
            }
        }
    }
}

// ================= mixed kernel: GEMM half0 + gather half1, interleaved =================
// blocks [0, 296): even -> gemm m-block b/2 (0..147), odd -> gather block b/2 (0..147)
// blocks [296, 344): gemm m-block 148 + (b - 296)  (148..195)
__global__ __launch_bounds__(256) void mixed_kernel(
    const float* __restrict__ feat,
    const float* __restrict__ b0, const float* __restrict__ b1,
    const float* __restrict__ b2, float* __restrict__ out)
{
    const int b = blockIdx.x;
    int gemm_idx = -1, gath_idx = -1;
    if (b < 296) {
        if ((b & 1) == 0) gemm_idx = b >> 1;
        else              gath_idx = b >> 1;
    } else {
        gemm_idx = 148 + (b - 296);
    }

    if (gemm_idx >= 0) {
        gemm_block(gemm_idx * 128, b0, b1, b2, out);
    } else {
        // gather rows [ROWS_H0, NN): 3 * ROWS_H1 tasks, grid-stride over NGATHER*8 warps
        const int lane = threadIdx.x & 31;
        const int wlocal = threadIdx.x >> 5;
        const int ntasks = 3 * ROWS_H1;
        const int stride = NGATHER * 8;
        for (int task = gath_idx * 8 + wlocal; task < ntasks; task += stride) {
            int seg  = task / ROWS_H1;
            int node = ROWS_H0 + (task - seg * ROWS_H1);
            gather_one(seg, node, lane, feat);
        }
    }
}

// ================= GEMM half 1 =================
__global__ __launch_bounds__(256) void gemm_h1_kernel(
    const float* __restrict__ b0, const float* __restrict__ b1,
    const float* __restrict__ b2, float* __restrict__ out)
{
    gemm_block((MB_H0 + blockIdx.x) * 128, b0, b1, b2, out);
}

// ================= launch =================
extern "C" void kernel_launch(void* const* d_in, const int* in_sizes, int n_in,
                              void* d_out, int out_size)
{
    const float* features = (const float*)d_in[0];
    const void*  src0 = d_in[1]; const void* dst0 = d_in[2];
    const void*  src1 = d_in[3]; const void* dst1 = d_in[4];
    const void*  src2 = d_in[5]; const void* dst2 = d_in[6];
    const float* W0 = (const float*)d_in[7];  const float* b0 = (const float*)d_in[8];
    const float* W1 = (const float*)d_in[9];  const float* b1 = (const float*)d_in[10];
    const float* W2 = (const float*)d_in[11]; const float* b2 = (const float*)d_in[12];
    float* out = (float*)d_out;

    cudaFuncSetAttribute(mixed_kernel,   cudaFuncAttributeMaxDynamicSharedMemorySize, SMEM_GEMM);
    cudaFuncSetAttribute(gemm_h1_kernel, cudaFuncAttributeMaxDynamicSharedMemorySize, SMEM_GEMM);

    const int nScanBlocks = (NSEG3 + 255) / 256;   // 586

    zero_detect_kernel<<<nScanBlocks, 256>>>((const int*)src0);

    {
        dim3 grid((EE + 255) / 256, 1, 3);
        hist_kernel<<<grid, 256>>>(dst0, dst1, dst2);
    }
    scan1_kernel<<<nScanBlocks, 256>>>();
    scan2_kernel<<<1, 1024>>>(nScanBlocks);
    {
        dim3 grid((EE + 255) / 256, 1, 3);
        scatter_kernel<<<grid, 256>>>(src0, dst0, src1, dst1, src2, dst2);
    }
    {
        dim3 grid(DD / 32, DD / 32, 3);
        convertB_kernel<<<grid, dim3(32, 8)>>>(W0, W1, W2);
    }
    {
        int ntasks = 3 * ROWS_H0;
        int blocks = (ntasks * 32 + 255) / 256;
        gather_h0_kernel<<<blocks, 256>>>(features);
    }
    mixed_kernel<<<NMIXED, 256, SMEM_GEMM>>>(features, b0, b1, b2, out);
    gemm_h1_kernel<<<MPAD / 128 - MB_H0, 256, SMEM_GEMM>>>(b0, b1, b2, out);
}

// round 8
// speedup vs baseline: 1.5120x; 1.5120x over previous
#include <cuda_runtime.h>
#include <cuda_bf16.h>
#include <cuda_fp16.h>
#include <cstdint>

#define NN   50000
#define EE   500000
#define DD   256
#define KTOT 768            // 3 * DD
#define MPAD 50048          // 391 * 128
#define NSEG3 (3 * NN)

// ---------------- scratch (static device globals; zero-initialized at load) ----------------
__device__ int            g_is64;
__device__ int            g_icnt[NSEG3];
__device__ int            g_cur[NSEG3];
__device__ int            g_off[NSEG3];
__device__ int            g_bsum[1024];
__device__ int            g_bsumx[1024];
__device__ int            g_csr[3 * EE];
__device__ float          g_flg[NSEG3];
__device__ unsigned short g_fh[(size_t)NN * DD];     // fp16 copy of features
__device__ unsigned short g_ah[(size_t)MPAD * KTOT]; // bf16 hi of mean-agg (rows>=NN stay 0)
__device__ unsigned short g_al[(size_t)MPAD * KTOT]; // bf16 lo
__device__ unsigned short g_bh[(size_t)DD * KTOT];   // B[n][k] = W_seg[k][n], bf16 hi
__device__ unsigned short g_bl[(size_t)DD * KTOT];   // bf16 lo

// ================= helpers =================
__device__ __forceinline__ uint32_t smem_u32(const void* p) {
    uint32_t a;
    asm("{ .reg .u64 t; cvta.to.shared.u64 t, %1; cvt.u32.u64 %0, t; }" : "=r"(a) : "l"(p));
    return a;
}
__device__ __forceinline__ uint32_t sw128(uint32_t b) { return b ^ ((b >> 3) & 0x70); }

__device__ __forceinline__ void cp16(uint32_t dst, const void* src) {
    asm volatile("cp.async.cg.shared.global [%0], [%1], 16;" :: "r"(dst), "l"(src));
}
__device__ __forceinline__ void ldm4(uint32_t* r, uint32_t addr) {
    asm volatile("ldmatrix.sync.aligned.m8n8.x4.shared.b16 {%0,%1,%2,%3}, [%4];"
                 : "=r"(r[0]), "=r"(r[1]), "=r"(r[2]), "=r"(r[3]) : "r"(addr));
}
__device__ __forceinline__ void mma_bf16(float* c, const uint32_t* a, const uint32_t* b) {
    asm volatile("mma.sync.aligned.m16n8k16.row.col.f32.bf16.bf16.f32 "
                 "{%0,%1,%2,%3}, {%4,%5,%6,%7}, {%8,%9}, {%0,%1,%2,%3};"
                 : "+f"(c[0]), "+f"(c[1]), "+f"(c[2]), "+f"(c[3])
                 : "r"(a[0]), "r"(a[1]), "r"(a[2]), "r"(a[3]), "r"(b[0]), "r"(b[1]));
}
__device__ __forceinline__ void bsplit(float a, unsigned short& h, unsigned short& l) {
    __nv_bfloat16 hb = __float2bfloat16_rn(a);
    float hf = __bfloat162float(hb);
    __nv_bfloat16 lb = __float2bfloat16_rn(a - hf);
    h = *reinterpret_cast<unsigned short*>(&hb);
    l = *reinterpret_cast<unsigned short*>(&lb);
}
__device__ __forceinline__ void acc8_from_u4(float* a, uint4 q) {
    __half2 p0 = *reinterpret_cast<__half2*>(&q.x);
    __half2 p1 = *reinterpret_cast<__half2*>(&q.y);
    __half2 p2 = *reinterpret_cast<__half2*>(&q.z);
    __half2 p3 = *reinterpret_cast<__half2*>(&q.w);
    float2 f0 = __half22float2(p0);
    float2 f1 = __half22float2(p1);
    float2 f2 = __half22float2(p2);
    float2 f3 = __half22float2(p3);
    a[0] += f0.x; a[1] += f0.y; a[2] += f1.x; a[3] += f1.y;
    a[4] += f2.x; a[5] += f2.y; a[6] += f3.x; a[7] += f3.y;
}

// ================= phase 0: detect + zero counters (merged) =================
__global__ void zero_detect_kernel(const int* __restrict__ src) {
    int i = blockIdx.x * blockDim.x + threadIdx.x;
    if (i < NSEG3) { g_icnt[i] = 0; g_cur[i] = 0; }
    if (i == 0) {
        int ok = 1;
#pragma unroll
        for (int k = 0; k < 32; k++)
            if (src[2 * k + 1] != 0) ok = 0;
        g_is64 = ok;
    }
}

// ================= phase 0b: features fp32 -> fp16 =================
__global__ __launch_bounds__(256) void convertF_kernel(const float* __restrict__ feat) {
    size_t i = (size_t)blockIdx.x * blockDim.x + threadIdx.x;   // one per 8 elems
    const size_t total = (size_t)NN * DD / 8;
    if (i >= total) return;
    float4 v0 = reinterpret_cast<const float4*>(feat)[2 * i];
    float4 v1 = reinterpret_cast<const float4*>(feat)[2 * i + 1];
    __half2 p0 = __floats2half2_rn(v0.x, v0.y);
    __half2 p1 = __floats2half2_rn(v0.z, v0.w);
    __half2 p2 = __floats2half2_rn(v1.x, v1.y);
    __half2 p3 = __floats2half2_rn(v1.z, v1.w);
    uint4 q;
    q.x = *reinterpret_cast<uint32_t*>(&p0);
    q.y = *reinterpret_cast<uint32_t*>(&p1);
    q.z = *reinterpret_cast<uint32_t*>(&p2);
    q.w = *reinterpret_cast<uint32_t*>(&p3);
    reinterpret_cast<uint4*>(g_fh)[i] = q;
}

// ================= phase 1: CSR build =================
__global__ __launch_bounds__(256) void hist_kernel(
    const void* __restrict__ dst0, const void* __restrict__ dst1,
    const void* __restrict__ dst2)
{
    int e = blockIdx.x * blockDim.x + threadIdx.x;
    if (e >= EE) return;
    const int seg = blockIdx.z;
    const void* dst = (seg == 0) ? dst0 : ((seg == 1) ? dst1 : dst2);
    int d = g_is64 ? (int)((const long long*)dst)[e] : ((const int*)dst)[e];
    if ((unsigned)d >= NN) return;
    atomicAdd(&g_icnt[seg * NN + d], 1);
}

__global__ __launch_bounds__(256) void scan1_kernel() {
    __shared__ int sh[256];
    int t = threadIdx.x;
    int i = blockIdx.x * 256 + t;
    int v = (i < NSEG3) ? g_icnt[i] : 0;
    sh[t] = v;
    __syncthreads();
    int acc = v;
#pragma unroll
    for (int ofs = 1; ofs < 256; ofs <<= 1) {
        int o = (t >= ofs) ? sh[t - ofs] : 0;
        __syncthreads();
        acc += o;
        sh[t] = acc;
        __syncthreads();
    }
    if (i < NSEG3) g_off[i] = acc - v;
    if (t == 255) g_bsum[blockIdx.x] = acc;
}

__global__ __launch_bounds__(1024) void scan2_kernel(int nblocks) {
    __shared__ int sh[1024];
    int t = threadIdx.x;
    int v = (t < nblocks) ? g_bsum[t] : 0;
    sh[t] = v;
    __syncthreads();
    int acc = v;
#pragma unroll
    for (int ofs = 1; ofs < 1024; ofs <<= 1) {
        int o = (t >= ofs) ? sh[t - ofs] : 0;
        __syncthreads();
        acc += o;
        sh[t] = acc;
        __syncthreads();
    }
    g_bsumx[t] = acc - v;
}

__global__ __launch_bounds__(256) void scatter_kernel(
    const void* __restrict__ src0, const void* __restrict__ dst0,
    const void* __restrict__ src1, const void* __restrict__ dst1,
    const void* __restrict__ src2, const void* __restrict__ dst2)
{
    int e = blockIdx.x * blockDim.x + threadIdx.x;
    if (e >= EE) return;
    const int seg = blockIdx.z;
    const void* src = (seg == 0) ? src0 : ((seg == 1) ? src1 : src2);
    const void* dst = (seg == 0) ? dst0 : ((seg == 1) ? dst1 : dst2);
    int s, d;
    if (g_is64) {
        s = (int)((const long long*)src)[e];
        d = (int)((const long long*)dst)[e];
    } else {
        s = ((const int*)src)[e];
        d = ((const int*)dst)[e];
    }
    if ((unsigned)s >= NN || (unsigned)d >= NN) return;
    int idx  = seg * NN + d;
    int base = g_off[idx] + g_bsumx[idx >> 8];
    int pos  = base + atomicAdd(&g_cur[idx], 1);
    g_csr[pos] = s;
}

// ================= phase 2: fused fp16 gather + mean + bf16 split =================
// one warp per (seg,node); lane covers elements [8*lane, 8*lane+8) of the 256-row
__global__ __launch_bounds__(256) void node_gather_kernel()
{
    int gw = (blockIdx.x * blockDim.x + threadIdx.x) >> 5;
    if (gw >= NSEG3) return;
    const int lane = threadIdx.x & 31;
    const int seg  = gw / NN;
    const int node = gw - seg * NN;

    const int deg  = g_icnt[gw];
    const int base = g_off[gw] + g_bsumx[gw >> 8];

    float a[8];
#pragma unroll
    for (int i = 0; i < 8; i++) a[i] = 0.f;

    int p = 0;
    for (; p + 3 < deg; p += 4) {            // 4 rows in flight -> MLP 4
        int s0 = g_csr[base + p];
        int s1 = g_csr[base + p + 1];
        int s2 = g_csr[base + p + 2];
        int s3 = g_csr[base + p + 3];
        uint4 q0 = __ldg(&reinterpret_cast<const uint4*>(g_fh + (size_t)s0 * DD)[lane]);
        uint4 q1 = __ldg(&reinterpret_cast<const uint4*>(g_fh + (size_t)s1 * DD)[lane]);
        uint4 q2 = __ldg(&reinterpret_cast<const uint4*>(g_fh + (size_t)s2 * DD)[lane]);
        uint4 q3 = __ldg(&reinterpret_cast<const uint4*>(g_fh + (size_t)s3 * DD)[lane]);
        acc8_from_u4(a, q0);
        acc8_from_u4(a, q1);
        acc8_from_u4(a, q2);
        acc8_from_u4(a, q3);
    }
    for (; p < deg; p++) {
        int s0 = g_csr[base + p];
        uint4 q0 = __ldg(&reinterpret_cast<const uint4*>(g_fh + (size_t)s0 * DD)[lane]);
        acc8_from_u4(a, q0);
    }

    const float inv = (deg > 0) ? (1.f / (float)deg) : 0.f;
    unsigned short h[8], l[8];
#pragma unroll
    for (int i = 0; i < 8; i++)
        bsplit(a[i] * inv, h[i], l[i]);

    unsigned short* rh = g_ah + (size_t)node * KTOT + seg * DD;
    unsigned short* rl = g_al + (size_t)node * KTOT + seg * DD;
    uint4 H, L;
    H.x = (uint32_t)h[0] | ((uint32_t)h[1] << 16);
    H.y = (uint32_t)h[2] | ((uint32_t)h[3] << 16);
    H.z = (uint32_t)h[4] | ((uint32_t)h[5] << 16);
    H.w = (uint32_t)h[6] | ((uint32_t)h[7] << 16);
    L.x = (uint32_t)l[0] | ((uint32_t)l[1] << 16);
    L.y = (uint32_t)l[2] | ((uint32_t)l[3] << 16);
    L.z = (uint32_t)l[4] | ((uint32_t)l[5] << 16);
    L.w = (uint32_t)l[6] | ((uint32_t)l[7] << 16);
    *reinterpret_cast<uint4*>(rh + 8 * lane) = H;
    *reinterpret_cast<uint4*>(rl + 8 * lane) = L;
    if (lane == 0)
        g_flg[gw] = (deg > 0) ? 1.f : 0.f;
}

// ================= phase 2b: B transpose + split =================
__global__ void convertB_kernel(const float* __restrict__ W0,
                                const float* __restrict__ W1,
                                const float* __restrict__ W2) {
    __shared__ float tile[32][33];
    const int seg = blockIdx.z;
    const float* W = (seg == 0) ? W0 : ((seg == 1) ? W1 : W2);
    const int kb = blockIdx.x * 32, nb = blockIdx.y * 32;
    const int tx = threadIdx.x, ty = threadIdx.y;
#pragma unroll
    for (int i = 0; i < 32; i += 8)
        tile[ty + i][tx] = W[(size_t)(kb + ty + i) * DD + nb + tx];
    __syncthreads();
#pragma unroll
    for (int i = 0; i < 32; i += 8) {
        int n = nb + ty + i, k = kb + tx;
        unsigned short h, l;
        bsplit(tile[tx][ty + i], h, l);
        g_bh[(size_t)n * KTOT + seg * DD + k] = h;
        g_bl[(size_t)n * KTOT + seg * DD + k] = l;
    }
}

// ================= phase 3: mma.sync bf16 GEMM (identical to R6 pass) =================
#define O_AH 0
#define O_AL 16384
#define O_BH 32768
#define O_BL 65536
#define STG_SZ 98304
#define NCHUNK 12
#define SMEM_GEMM (2 * STG_SZ)

__device__ __forceinline__ void load_chunk(int kc, uint32_t stg, int t, int m0) {
    const char* ahg = (const char*)g_ah + ((size_t)m0 * KTOT + kc * 64) * 2;
    const char* alg = (const char*)g_al + ((size_t)m0 * KTOT + kc * 64) * 2;
    const char* bhg = (const char*)g_bh + ((size_t)kc * 64) * 2;
    const char* blg = (const char*)g_bl + ((size_t)kc * 64) * 2;
#pragma unroll
    for (int i = t; i < 1024; i += 256) {
        int r = i >> 3, j = (i & 7) * 16;
        uint32_t so = sw128(r * 128 + j);
        size_t  go = (size_t)r * (KTOT * 2) + j;
        cp16(stg + O_AH + so, ahg + go);
        cp16(stg + O_AL + so, alg + go);
    }
#pragma unroll
    for (int i = t; i < 2048; i += 256) {
        int r = i >> 3, j = (i & 7) * 16;
        uint32_t so = sw128(r * 128 + j);
        size_t  go = (size_t)r * (KTOT * 2) + j;
        cp16(stg + O_BH + so, bhg + go);
        cp16(stg + O_BL + so, blg + go);
    }
    asm volatile("cp.async.commit_group;" ::: "memory");
}

__global__ __launch_bounds__(256) void gemm_mma_kernel(
    const float* __restrict__ b0, const float* __restrict__ b1,
    const float* __restrict__ b2, float* __restrict__ out)
{
    extern __shared__ char smem[];
    const uint32_t sb = smem_u32(smem);
    const int t = threadIdx.x, wid = t >> 5, lane = t & 31;
    const int m0 = blockIdx.x * 128;
    const int wm = wid & 1, wn = wid >> 1;

    float acc[4][8][4];
#pragma unroll
    for (int i = 0; i < 4; i++)
#pragma unroll
        for (int j = 0; j < 8; j++)
#pragma unroll
            for (int k = 0; k < 4; k++) acc[i][j][k] = 0.f;

    load_chunk(0, sb, t, m0);
    load_chunk(1, sb + STG_SZ, t, m0);

    const uint32_t arow  = (uint32_t)(wm * 64 + (lane & 15));
    const uint32_t acol8 = (uint32_t)(lane >> 4);
    const uint32_t brow  = (uint32_t)(wn * 64 + (lane & 7) + ((lane >> 4) & 1) * 8);
    const uint32_t bcol8 = (uint32_t)((lane >> 3) & 1);

#pragma unroll 1
    for (int c = 0; c < NCHUNK; c++) {
        const uint32_t stg = sb + (uint32_t)(c & 1) * STG_SZ;

        asm volatile("cp.async.wait_group 1;" ::: "memory");
        __syncthreads();

#pragma unroll
        for (int ks = 0; ks < 4; ks++) {
            uint32_t ah[4][4], al[4][4];
#pragma unroll
            for (int mf = 0; mf < 4; mf++) {
                uint32_t off = sw128((arow + mf * 16) * 128 + (ks * 16 + acol8 * 8) * 2);
                ldm4(ah[mf], stg + O_AH + off);
                ldm4(al[mf], stg + O_AL + off);
            }
#pragma unroll
            for (int nf2 = 0; nf2 < 4; nf2++) {
                uint32_t bh[4], bl[4];
                uint32_t off = sw128((brow + nf2 * 16) * 128 + (ks * 16 + bcol8 * 8) * 2);
                ldm4(bh, stg + O_BH + off);
                ldm4(bl, stg + O_BL + off);
#pragma unroll
                for (int mf = 0; mf < 4; mf++)
#pragma unroll
                    for (int j = 0; j < 2; j++) {
                        float* a = acc[mf][nf2 * 2 + j];
                        mma_bf16(a, ah[mf], &bh[2 * j]);
                        mma_bf16(a, ah[mf], &bl[2 * j]);
                        mma_bf16(a, al[mf], &bh[2 * j]);
                    }
            }
        }

        __syncthreads();
        if (c + 2 < NCHUNK)
            load_chunk(c + 2, sb + (uint32_t)(c & 1) * STG_SZ, t, m0);
    }

    const int gid = lane >> 2, t4 = lane & 3;
    float2 bb0[8], bb1[8], bb2[8];
#pragma unroll
    for (int nf = 0; nf < 8; nf++) {
        int col = wn * 64 + nf * 8 + t4 * 2;
        bb0[nf] = *reinterpret_cast<const float2*>(b0 + col);
        bb1[nf] = *reinterpret_cast<const float2*>(b1 + col);
        bb2[nf] = *reinterpret_cast<const float2*>(b2 + col);
    }
#pragma unroll
    for (int mf = 0; mf < 4; mf++) {
#pragma unroll
        for (int half = 0; half < 2; half++) {
            int row = m0 + wm * 64 + mf * 16 + gid + half * 8;
            if (row >= NN) continue;
            float f0 = g_flg[row], f1 = g_flg[NN + row], f2 = g_flg[2 * NN + row];
#pragma unroll
            for (int nf = 0; nf < 8; nf++) {
                int col = wn * 64 + nf * 8 + t4 * 2;
                float2 o;
                o.x = fmaxf(acc[mf][nf][2 * half]     + f0 * bb0[nf].x + f1 * bb1[nf].x + f2 * bb2[nf].x, 0.f);
                o.y = fmaxf(acc[mf][nf][2 * half + 1] + f0 * bb0[nf].y + f1 * bb1[nf].y + f2 * bb2[nf].y, 0.f);
                *reinterpret_cast<float2*>(out + (size_t)row * DD + col) = o;
            }
        }
    }
}

// ================= launch =================
extern "C" void kernel_launch(void* const* d_in, const int* in_sizes, int n_in,
                              void* d_out, int out_size)
{
    const float* features = (const float*)d_in[0];
    const void*  src0 = d_in[1]; const void* dst0 = d_in[2];
    const void*  src1 = d_in[3]; const void* dst1 = d_in[4];
    const void*  src2 = d_in[5]; const void* dst2 = d_in[6];
    const float* W0 = (const float*)d_in[7];  const float* b0 = (const float*)d_in[8];
    const float* W1 = (const float*)d_in[9];  const float* b1 = (const float*)d_in[10];
    const float* W2 = (const float*)d_in[11]; const float* b2 = (const float*)d_in[12];
    float* out = (float*)d_out;

    cudaFuncSetAttribute(gemm_mma_kernel, cudaFuncAttributeMaxDynamicSharedMemorySize,
                         SMEM_GEMM);

    const int nScanBlocks = (NSEG3 + 255) / 256;   // 586

    zero_detect_kernel<<<nScanBlocks, 256>>>((const int*)src0);
    {
        size_t total = (size_t)NN * DD / 8;        // 1.6M threads
        convertF_kernel<<<(int)((total + 255) / 256), 256>>>(features);
    }
    {
        dim3 grid((EE + 255) / 256, 1, 3);
        hist_kernel<<<grid, 256>>>(dst0, dst1, dst2);
    }
    scan1_kernel<<<nScanBlocks, 256>>>();
    scan2_kernel<<<1, 1024>>>(nScanBlocks);
    {
        dim3 grid((EE + 255) / 256, 1, 3);
        scatter_kernel<<<grid, 256>>>(src0, dst0, src1, dst1, src2, dst2);
    }
    {
        int blocks = (NSEG3 * 32 + 255) / 256;
        node_gather_kernel<<<blocks, 256>>>();
    }
    {
        dim3 grid(DD / 32, DD / 32, 3);
        convertB_kernel<<<grid, dim3(32, 8)>>>(W0, W1, W2);
    }
    {
        dim3 grid(MPAD / 128, 1);
        gemm_mma_kernel<<<grid, 256, SMEM_GEMM>>>(b0, b1, b2, out);
    }
}

// round 10
// speedup vs baseline: 1.8872x; 1.2481x over previous
#include <cuda_runtime.h>
#include <cuda_bf16.h>
#include <cuda_fp16.h>
#include <cstdint>

#define NN   50000
#define EE   500000
#define DD   256
#define KTOT 768            // 3 * DD
#define MPAD 50048          // 391 * 128
#define NSEG3 (3 * NN)

// ---------------- scratch (static device globals; zero-initialized at load) ----------------
__device__ int            g_is64;
__device__ int            g_icnt[NSEG3];
__device__ int            g_cur[NSEG3];
__device__ int            g_off[NSEG3];
__device__ int            g_bsum[1024];
__device__ int            g_bsumx[1024];
__device__ int            g_csr[3 * EE];
__device__ float          g_flg[NSEG3];
__device__ unsigned short g_fh[(size_t)NN * DD];     // fp16 copy of features
__device__ unsigned short g_a [(size_t)MPAD * KTOT]; // fp16 mean-agg A (rows>=NN stay 0)
__device__ unsigned short g_bh[(size_t)DD * KTOT];   // B[n][k] = W_seg[k][n], fp16 hi
__device__ unsigned short g_bl[(size_t)DD * KTOT];   // fp16 lo (residual)

// ================= helpers =================
__device__ __forceinline__ uint32_t smem_u32(const void* p) {
    uint32_t a;
    asm("{ .reg .u64 t; cvta.to.shared.u64 t, %1; cvt.u32.u64 %0, t; }" : "=r"(a) : "l"(p));
    return a;
}
__device__ __forceinline__ uint32_t sw128(uint32_t b) { return b ^ ((b >> 3) & 0x70); }

__device__ __forceinline__ void cp16(uint32_t dst, const void* src) {
    asm volatile("cp.async.cg.shared.global [%0], [%1], 16;" :: "r"(dst), "l"(src));
}
__device__ __forceinline__ void ldm4(uint32_t* r, uint32_t addr) {
    asm volatile("ldmatrix.sync.aligned.m8n8.x4.shared.b16 {%0,%1,%2,%3}, [%4];"
                 : "=r"(r[0]), "=r"(r[1]), "=r"(r[2]), "=r"(r[3]) : "r"(addr));
}
__device__ __forceinline__ void mma_f16(float* c, const uint32_t* a, const uint32_t* b) {
    asm volatile("mma.sync.aligned.m16n8k16.row.col.f32.f16.f16.f32 "
                 "{%0,%1,%2,%3}, {%4,%5,%6,%7}, {%8,%9}, {%0,%1,%2,%3};"
                 : "+f"(c[0]), "+f"(c[1]), "+f"(c[2]), "+f"(c[3])
                 : "r"(a[0]), "r"(a[1]), "r"(a[2]), "r"(a[3]), "r"(b[0]), "r"(b[1]));
}
__device__ __forceinline__ void hsplit(float a, unsigned short& h, unsigned short& l) {
    __half hb = __float2half_rn(a);
    float hf = __half2float(hb);
    __half lb = __float2half_rn(a - hf);
    h = *reinterpret_cast<unsigned short*>(&hb);
    l = *reinterpret_cast<unsigned short*>(&lb);
}
__device__ __forceinline__ void acc8_from_u4(float* a, uint4 q) {
    __half2 p0 = *reinterpret_cast<__half2*>(&q.x);
    __half2 p1 = *reinterpret_cast<__half2*>(&q.y);
    __half2 p2 = *reinterpret_cast<__half2*>(&q.z);
    __half2 p3 = *reinterpret_cast<__half2*>(&q.w);
    float2 f0 = __half22float2(p0);
    float2 f1 = __half22float2(p1);
    float2 f2 = __half22float2(p2);
    float2 f3 = __half22float2(p3);
    a[0] += f0.x; a[1] += f0.y; a[2] += f1.x; a[3] += f1.y;
    a[4] += f2.x; a[5] += f2.y; a[6] += f3.x; a[7] += f3.y;
}

// ================= phase 0: detect + zero counters (merged) =================
__global__ void zero_detect_kernel(const int* __restrict__ src) {
    int i = blockIdx.x * blockDim.x + threadIdx.x;
    if (i < NSEG3) { g_icnt[i] = 0; g_cur[i] = 0; }
    if (i == 0) {
        int ok = 1;
#pragma unroll
        for (int k = 0; k < 32; k++)
            if (src[2 * k + 1] != 0) ok = 0;
        g_is64 = ok;
    }
}

// ================= phase 0b: features fp32 -> fp16 =================
__global__ __launch_bounds__(256) void convertF_kernel(const float* __restrict__ feat) {
    size_t i = (size_t)blockIdx.x * blockDim.x + threadIdx.x;   // one per 8 elems
    const size_t total = (size_t)NN * DD / 8;
    if (i >= total) return;
    float4 v0 = reinterpret_cast<const float4*>(feat)[2 * i];
    float4 v1 = reinterpret_cast<const float4*>(feat)[2 * i + 1];
    __half2 p0 = __floats2half2_rn(v0.x, v0.y);
    __half2 p1 = __floats2half2_rn(v0.z, v0.w);
    __half2 p2 = __floats2half2_rn(v1.x, v1.y);
    __half2 p3 = __floats2half2_rn(v1.z, v1.w);
    uint4 q;
    q.x = *reinterpret_cast<uint32_t*>(&p0);
    q.y = *reinterpret_cast<uint32_t*>(&p1);
    q.z = *reinterpret_cast<uint32_t*>(&p2);
    q.w = *reinterpret_cast<uint32_t*>(&p3);
    reinterpret_cast<uint4*>(g_fh)[i] = q;
}

// ================= phase 1: CSR build =================
__global__ __launch_bounds__(256) void hist_kernel(
    const void* __restrict__ dst0, const void* __restrict__ dst1,
    const void* __restrict__ dst2)
{
    int e = blockIdx.x * blockDim.x + threadIdx.x;
    if (e >= EE) return;
    const int seg = blockIdx.z;
    const void* dst = (seg == 0) ? dst0 : ((seg == 1) ? dst1 : dst2);
    int d = g_is64 ? (int)((const long long*)dst)[e] : ((const int*)dst)[e];
    if ((unsigned)d >= NN) return;
    atomicAdd(&g_icnt[seg * NN + d], 1);
}

__global__ __launch_bounds__(256) void scan1_kernel() {
    __shared__ int sh[256];
    int t = threadIdx.x;
    int i = blockIdx.x * 256 + t;
    int v = (i < NSEG3) ? g_icnt[i] : 0;
    sh[t] = v;
    __syncthreads();
    int acc = v;
#pragma unroll
    for (int ofs = 1; ofs < 256; ofs <<= 1) {
        int o = (t >= ofs) ? sh[t - ofs] : 0;
        __syncthreads();
        acc += o;
        sh[t] = acc;
        __syncthreads();
    }
    if (i < NSEG3) g_off[i] = acc - v;
    if (t == 255) g_bsum[blockIdx.x] = acc;
}

__global__ __launch_bounds__(1024) void scan2_kernel(int nblocks) {
    __shared__ int sh[1024];
    int t = threadIdx.x;
    int v = (t < nblocks) ? g_bsum[t] : 0;
    sh[t] = v;
    __syncthreads();
    int acc = v;
#pragma unroll
    for (int ofs = 1; ofs < 1024; ofs <<= 1) {
        int o = (t >= ofs) ? sh[t - ofs] : 0;
        __syncthreads();
        acc += o;
        sh[t] = acc;
        __syncthreads();
    }
    g_bsumx[t] = acc - v;
}

__global__ __launch_bounds__(256) void scatter_kernel(
    const void* __restrict__ src0, const void* __restrict__ dst0,
    const void* __restrict__ src1, const void* __restrict__ dst1,
    const void* __restrict__ src2, const void* __restrict__ dst2)
{
    int e = blockIdx.x * blockDim.x + threadIdx.x;
    if (e >= EE) return;
    const int seg = blockIdx.z;
    const void* src = (seg == 0) ? src0 : ((seg == 1) ? src1 : src2);
    const void* dst = (seg == 0) ? dst0 : ((seg == 1) ? dst1 : dst2);
    int s, d;
    if (g_is64) {
        s = (int)((const long long*)src)[e];
        d = (int)((const long long*)dst)[e];
    } else {
        s = ((const int*)src)[e];
        d = ((const int*)dst)[e];
    }
    if ((unsigned)s >= NN || (unsigned)d >= NN) return;
    int idx  = seg * NN + d;
    int base = g_off[idx] + g_bsumx[idx >> 8];
    int pos  = base + atomicAdd(&g_cur[idx], 1);
    g_csr[pos] = s;
}

// ================= phase 2: fused fp16 gather + mean -> fp16 A =================
// one warp per (seg,node); lane covers elements [8*lane, 8*lane+8) of the 256-row
__global__ __launch_bounds__(256) void node_gather_kernel()
{
    int gw = (blockIdx.x * blockDim.x + threadIdx.x) >> 5;
    if (gw >= NSEG3) return;
    const int lane = threadIdx.x & 31;
    const int seg  = gw / NN;
    const int node = gw - seg * NN;

    const int deg  = g_icnt[gw];
    const int base = g_off[gw] + g_bsumx[gw >> 8];

    float a[8];
#pragma unroll
    for (int i = 0; i < 8; i++) a[i] = 0.f;

    int p = 0;
    for (; p + 3 < deg; p += 4) {            // 4 rows in flight -> MLP 4
        int s0 = g_csr[base + p];
        int s1 = g_csr[base + p + 1];
        int s2 = g_csr[base + p + 2];
        int s3 = g_csr[base + p + 3];
        uint4 q0 = __ldg(&reinterpret_cast<const uint4*>(g_fh + (size_t)s0 * DD)[lane]);
        uint4 q1 = __ldg(&reinterpret_cast<const uint4*>(g_fh + (size_t)s1 * DD)[lane]);
        uint4 q2 = __ldg(&reinterpret_cast<const uint4*>(g_fh + (size_t)s2 * DD)[lane]);
        uint4 q3 = __ldg(&reinterpret_cast<const uint4*>(g_fh + (size_t)s3 * DD)[lane]);
        acc8_from_u4(a, q0);
        acc8_from_u4(a, q1);
        acc8_from_u4(a, q2);
        acc8_from_u4(a, q3);
    }
    for (; p < deg; p++) {
        int s0 = g_csr[base + p];
        uint4 q0 = __ldg(&reinterpret_cast<const uint4*>(g_fh + (size_t)s0 * DD)[lane]);
        acc8_from_u4(a, q0);
    }

    const float inv = (deg > 0) ? (1.f / (float)deg) : 0.f;
    __half2 p0 = __floats2half2_rn(a[0] * inv, a[1] * inv);
    __half2 p1 = __floats2half2_rn(a[2] * inv, a[3] * inv);
    __half2 p2 = __floats2half2_rn(a[4] * inv, a[5] * inv);
    __half2 p3 = __floats2half2_rn(a[6] * inv, a[7] * inv);
    uint4 Q;
    Q.x = *reinterpret_cast<uint32_t*>(&p0);
    Q.y = *reinterpret_cast<uint32_t*>(&p1);
    Q.z = *reinterpret_cast<uint32_t*>(&p2);
    Q.w = *reinterpret_cast<uint32_t*>(&p3);
    unsigned short* ra = g_a + (size_t)node * KTOT + seg * DD;
    *reinterpret_cast<uint4*>(ra + 8 * lane) = Q;
    if (lane == 0)
        g_flg[gw] = (deg > 0) ? 1.f : 0.f;
}

// ================= phase 2b: B transpose + fp16 split =================
__global__ void convertB_kernel(const float* __restrict__ W0,
                                const float* __restrict__ W1,
                                const float* __restrict__ W2) {
    __shared__ float tile[32][33];
    const int seg = blockIdx.z;
    const float* W = (seg == 0) ? W0 : ((seg == 1) ? W1 : W2);
    const int kb = blockIdx.x * 32, nb = blockIdx.y * 32;
    const int tx = threadIdx.x, ty = threadIdx.y;
#pragma unroll
    for (int i = 0; i < 32; i += 8)
        tile[ty + i][tx] = W[(size_t)(kb + ty + i) * DD + nb + tx];
    __syncthreads();
#pragma unroll
    for (int i = 0; i < 32; i += 8) {
        int n = nb + ty + i, k = kb + tx;
        unsigned short h, l;
        hsplit(tile[tx][ty + i], h, l);
        g_bh[(size_t)n * KTOT + seg * DD + k] = h;
        g_bl[(size_t)n * KTOT + seg * DD + k] = l;
    }
}

// ================= phase 3: mma.sync fp16 GEMM, 2 passes (A*Bh + A*Bl) =================
// CTA 128(M) x 256(N), BK=64. Warp tile 64x64, 8 warps 2x4.
// Stage: A(16K) BH(32K) BL(32K) = 80KB; 2 stages = 160KB.
#define O_A  0
#define O_BH 16384
#define O_BL 49152
#define STG_SZ 81920
#define NCHUNK 12
#define SMEM_GEMM (2 * STG_SZ)

__device__ __forceinline__ void load_chunk(int kc, uint32_t stg, int t, int m0) {
    const char* ag  = (const char*)g_a  + ((size_t)m0 * KTOT + kc * 64) * 2;
    const char* bhg = (const char*)g_bh + ((size_t)kc * 64) * 2;
    const char* blg = (const char*)g_bl + ((size_t)kc * 64) * 2;
#pragma unroll
    for (int i = t; i < 1024; i += 256) {      // A: 128 rows x 128B
        int r = i >> 3, j = (i & 7) * 16;
        cp16(stg + O_A + sw128(r * 128 + j), ag + (size_t)r * (KTOT * 2) + j);
    }
#pragma unroll
    for (int i = t; i < 2048; i += 256) {      // B: 256 rows x 128B (hi + lo)
        int r = i >> 3, j = (i & 7) * 16;
        uint32_t so = sw128(r * 128 + j);
        size_t  go = (size_t)r * (KTOT * 2) + j;
        cp16(stg + O_BH + so, bhg + go);
        cp16(stg + O_BL + so, blg + go);
    }
    asm volatile("cp.async.commit_group;" ::: "memory");
}

__global__ __launch_bounds__(256) void gemm_mma_kernel(
    const float* __restrict__ b0, const float* __restrict__ b1,
    const float* __restrict__ b2, float* __restrict__ out)
{
    extern __shared__ char smem[];
    const uint32_t sb = smem_u32(smem);
    const int t = threadIdx.x, wid = t >> 5, lane = t & 31;
    const int m0 = blockIdx.x * 128;
    const int wm = wid & 1, wn = wid >> 1;

    float acc[4][8][4];
#pragma unroll
    for (int i = 0; i < 4; i++)
#pragma unroll
        for (int j = 0; j < 8; j++)
#pragma unroll
            for (int k = 0; k < 4; k++) acc[i][j][k] = 0.f;

    load_chunk(0, sb, t, m0);
    load_chunk(1, sb + STG_SZ, t, m0);

    const uint32_t arow  = (uint32_t)(wm * 64 + (lane & 15));
    const uint32_t acol8 = (uint32_t)(lane >> 4);
    const uint32_t brow  = (uint32_t)(wn * 64 + (lane & 7) + ((lane >> 4) & 1) * 8);
    const uint32_t bcol8 = (uint32_t)((lane >> 3) & 1);

#pragma unroll 1
    for (int c = 0; c < NCHUNK; c++) {
        const uint32_t stg = sb + (uint32_t)(c & 1) * STG_SZ;

        asm volatile("cp.async.wait_group 1;" ::: "memory");
        __syncthreads();

#pragma unroll
        for (int ks = 0; ks < 4; ks++) {
            uint32_t av[4][4];
#pragma unroll
            for (int mf = 0; mf < 4; mf++) {
                uint32_t off = sw128((arow + mf * 16) * 128 + (ks * 16 + acol8 * 8) * 2);
                ldm4(av[mf], stg + O_A + off);
            }
#pragma unroll
            for (int nf2 = 0; nf2 < 4; nf2++) {
                uint32_t bh[4], bl[4];
                uint32_t off = sw128((brow + nf2 * 16) * 128 + (ks * 16 + bcol8 * 8) * 2);
                ldm4(bh, stg + O_BH + off);
                ldm4(bl, stg + O_BL + off);
#pragma unroll
                for (int mf = 0; mf < 4; mf++)
#pragma unroll
                    for (int j = 0; j < 2; j++) {
                        float* a = acc[mf][nf2 * 2 + j];
                        mma_f16(a, av[mf], &bh[2 * j]);   // A*Bh
                        mma_f16(a, av[mf], &bl[2 * j]);   // A*Bl
                    }
            }
        }

        __syncthreads();
        if (c + 2 < NCHUNK)
            load_chunk(c + 2, sb + (uint32_t)(c & 1) * STG_SZ, t, m0);
    }

    const int gid = lane >> 2, t4 = lane & 3;
    float2 bb0[8], bb1[8], bb2[8];
#pragma unroll
    for (int nf = 0; nf < 8; nf++) {
        int col = wn * 64 + nf * 8 + t4 * 2;
        bb0[nf] = *reinterpret_cast<const float2*>(b0 + col);
        bb1[nf] = *reinterpret_cast<const float2*>(b1 + col);
        bb2[nf] = *reinterpret_cast<const float2*>(b2 + col);
    }
#pragma unroll
    for (int mf = 0; mf < 4; mf++) {
#pragma unroll
        for (int half = 0; half < 2; half++) {
            int row = m0 + wm * 64 + mf * 16 + gid + half * 8;
            if (row >= NN) continue;
            float f0 = g_flg[row], f1 = g_flg[NN + row], f2 = g_flg[2 * NN + row];
#pragma unroll
            for (int nf = 0; nf < 8; nf++) {
                int col = wn * 64 + nf * 8 + t4 * 2;
                float2 o;
                o.x = fmaxf(acc[mf][nf][2 * half]     + f0 * bb0[nf].x + f1 * bb1[nf].x + f2 * bb2[nf].x, 0.f);
                o.y = fmaxf(acc[mf][nf][2 * half + 1] + f0 * bb0[nf].y + f1 * bb1[nf].y + f2 * bb2[nf].y, 0.f);
                *reinterpret_cast<float2*>(out + (size_t)row * DD + col) = o;
            }
        }
    }
}

// ================= launch =================
extern "C" void kernel_launch(void* const* d_in, const int* in_sizes, int n_in,
                              void* d_out, int out_size)
{
    const float* features = (const float*)d_in[0];
    const void*  src0 = d_in[1]; const void* dst0 = d_in[2];
    const void*  src1 = d_in[3]; const void* dst1 = d_in[4];
    const void*  src2 = d_in[5]; const void* dst2 = d_in[6];
    const float* W0 = (const float*)d_in[7];  const float* b0 = (const float*)d_in[8];
    const float* W1 = (const float*)d_in[9];  const float* b1 = (const float*)d_in[10];
    const float* W2 = (const float*)d_in[11]; const float* b2 = (const float*)d_in[12];
    float* out = (float*)d_out;

    cudaFuncSetAttribute(gemm_mma_kernel, cudaFuncAttributeMaxDynamicSharedMemorySize,
                         SMEM_GEMM);

    const int nScanBlocks = (NSEG3 + 255) / 256;   // 586

    zero_detect_kernel<<<nScanBlocks, 256>>>((const int*)src0);
    {
        size_t total = (size_t)NN * DD / 8;
        convertF_kernel<<<(int)((total + 255) / 256), 256>>>(features);
    }
    {
        dim3 grid((EE + 255) / 256, 1, 3);
        hist_kernel<<<grid, 256>>>(dst0, dst1, dst2);
    }
    scan1_kernel<<<nScanBlocks, 256>>>();
    scan2_kernel<<<1, 1024>>>(nScanBlocks);
    {
        dim3 grid((EE + 255) / 256, 1, 3);
        scatter_kernel<<<grid, 256>>>(src0, dst0, src1, dst1, src2, dst2);
    }
    {
        int blocks = (NSEG3 * 32 + 255) / 256;
        node_gather_kernel<<<blocks, 256>>>();
    }
    {
        dim3 grid(DD / 32, DD / 32, 3);
        convertB_kernel<<<grid, dim3(32, 8)>>>(W0, W1, W2);
    }
    {
        dim3 grid(MPAD / 128, 1);
        gemm_mma_kernel<<<grid, 256, SMEM_GEMM>>>(b0, b1, b2, out);
    }
}

// round 11
// speedup vs baseline: 2.3329x; 1.2362x over previous
#include <cuda_runtime.h>
#include <cuda_bf16.h>
#include <cuda_fp16.h>
#include <cstdint>

#define NN   50000
#define EE   500000
#define DD   256
#define KTOT 768            // 3 * DD
#define MPAD 50048          // 391 * 128
#define NSEG3 (3 * NN)

// ---------------- scratch (static device globals; zero-initialized at load) ----------------
__device__ int            g_is64;
__device__ int            g_icnt[NSEG3];
__device__ int            g_cur[NSEG3];
__device__ int            g_off[NSEG3];
__device__ int            g_bsum[1024];
__device__ int            g_bsumx[1024];
__device__ int            g_csr[3 * EE];
__device__ float          g_flg[NSEG3];
__device__ unsigned short g_fh[(size_t)NN * DD];     // fp16 copy of features
__device__ unsigned short g_a [(size_t)MPAD * KTOT]; // fp16 mean-agg A (rows>=NN stay 0)
__device__ unsigned short g_b [(size_t)DD * KTOT];   // B[n][k] = W_seg[k][n], fp16

// ================= helpers =================
__device__ __forceinline__ uint32_t smem_u32(const void* p) {
    uint32_t a;
    asm("{ .reg .u64 t; cvta.to.shared.u64 t, %1; cvt.u32.u64 %0, t; }" : "=r"(a) : "l"(p));
    return a;
}
__device__ __forceinline__ uint32_t sw128(uint32_t b) { return b ^ ((b >> 3) & 0x70); }

__device__ __forceinline__ void cp16(uint32_t dst, const void* src) {
    asm volatile("cp.async.cg.shared.global [%0], [%1], 16;" :: "r"(dst), "l"(src));
}
__device__ __forceinline__ void ldm4(uint32_t* r, uint32_t addr) {
    asm volatile("ldmatrix.sync.aligned.m8n8.x4.shared.b16 {%0,%1,%2,%3}, [%4];"
                 : "=r"(r[0]), "=r"(r[1]), "=r"(r[2]), "=r"(r[3]) : "r"(addr));
}
__device__ __forceinline__ void mma_f16(float* c, const uint32_t* a, const uint32_t* b) {
    asm volatile("mma.sync.aligned.m16n8k16.row.col.f32.f16.f16.f32 "
                 "{%0,%1,%2,%3}, {%4,%5,%6,%7}, {%8,%9}, {%0,%1,%2,%3};"
                 : "+f"(c[0]), "+f"(c[1]), "+f"(c[2]), "+f"(c[3])
                 : "r"(a[0]), "r"(a[1]), "r"(a[2]), "r"(a[3]), "r"(b[0]), "r"(b[1]));
}
__device__ __forceinline__ void acc8_from_u4(float* a, uint4 q) {
    __half2 p0 = *reinterpret_cast<__half2*>(&q.x);
    __half2 p1 = *reinterpret_cast<__half2*>(&q.y);
    __half2 p2 = *reinterpret_cast<__half2*>(&q.z);
    __half2 p3 = *reinterpret_cast<__half2*>(&q.w);
    float2 f0 = __half22float2(p0);
    float2 f1 = __half22float2(p1);
    float2 f2 = __half22float2(p2);
    float2 f3 = __half22float2(p3);
    a[0] += f0.x; a[1] += f0.y; a[2] += f1.x; a[3] += f1.y;
    a[4] += f2.x; a[5] += f2.y; a[6] += f3.x; a[7] += f3.y;
}

// ================= phase 0: detect + zero counters (merged) =================
__global__ void zero_detect_kernel(const int* __restrict__ src) {
    int i = blockIdx.x * blockDim.x + threadIdx.x;
    if (i < NSEG3) { g_icnt[i] = 0; g_cur[i] = 0; }
    if (i == 0) {
        int ok = 1;
#pragma unroll
        for (int k = 0; k < 32; k++)
            if (src[2 * k + 1] != 0) ok = 0;
        g_is64 = ok;
    }
}

// ================= phase 0b: features fp32 -> fp16 =================
__global__ __launch_bounds__(256) void convertF_kernel(const float* __restrict__ feat) {
    size_t i = (size_t)blockIdx.x * blockDim.x + threadIdx.x;   // one per 8 elems
    const size_t total = (size_t)NN * DD / 8;
    if (i >= total) return;
    float4 v0 = reinterpret_cast<const float4*>(feat)[2 * i];
    float4 v1 = reinterpret_cast<const float4*>(feat)[2 * i + 1];
    __half2 p0 = __floats2half2_rn(v0.x, v0.y);
    __half2 p1 = __floats2half2_rn(v0.z, v0.w);
    __half2 p2 = __floats2half2_rn(v1.x, v1.y);
    __half2 p3 = __floats2half2_rn(v1.z, v1.w);
    uint4 q;
    q.x = *reinterpret_cast<uint32_t*>(&p0);
    q.y = *reinterpret_cast<uint32_t*>(&p1);
    q.z = *reinterpret_cast<uint32_t*>(&p2);
    q.w = *reinterpret_cast<uint32_t*>(&p3);
    reinterpret_cast<uint4*>(g_fh)[i] = q;
}

// ================= phase 1: CSR build =================
__global__ __launch_bounds__(256) void hist_kernel(
    const void* __restrict__ dst0, const void* __restrict__ dst1,
    const void* __restrict__ dst2)
{
    int e = blockIdx.x * blockDim.x + threadIdx.x;
    if (e >= EE) return;
    const int seg = blockIdx.z;
    const void* dst = (seg == 0) ? dst0 : ((seg == 1) ? dst1 : dst2);
    int d = g_is64 ? (int)((const long long*)dst)[e] : ((const int*)dst)[e];
    if ((unsigned)d >= NN) return;
    atomicAdd(&g_icnt[seg * NN + d], 1);
}

__global__ __launch_bounds__(256) void scan1_kernel() {
    __shared__ int sh[256];
    int t = threadIdx.x;
    int i = blockIdx.x * 256 + t;
    int v = (i < NSEG3) ? g_icnt[i] : 0;
    sh[t] = v;
    __syncthreads();
    int acc = v;
#pragma unroll
    for (int ofs = 1; ofs < 256; ofs <<= 1) {
        int o = (t >= ofs) ? sh[t - ofs] : 0;
        __syncthreads();
        acc += o;
        sh[t] = acc;
        __syncthreads();
    }
    if (i < NSEG3) g_off[i] = acc - v;
    if (t == 255) g_bsum[blockIdx.x] = acc;
}

__global__ __launch_bounds__(1024) void scan2_kernel(int nblocks) {
    __shared__ int sh[1024];
    int t = threadIdx.x;
    int v = (t < nblocks) ? g_bsum[t] : 0;
    sh[t] = v;
    __syncthreads();
    int acc = v;
#pragma unroll
    for (int ofs = 1; ofs < 1024; ofs <<= 1) {
        int o = (t >= ofs) ? sh[t - ofs] : 0;
        __syncthreads();
        acc += o;
        sh[t] = acc;
        __syncthreads();
    }
    g_bsumx[t] = acc - v;
}

__global__ __launch_bounds__(256) void scatter_kernel(
    const void* __restrict__ src0, const void* __restrict__ dst0,
    const void* __restrict__ src1, const void* __restrict__ dst1,
    const void* __restrict__ src2, const void* __restrict__ dst2)
{
    int e = blockIdx.x * blockDim.x + threadIdx.x;
    if (e >= EE) return;
    const int seg = blockIdx.z;
    const void* src = (seg == 0) ? src0 : ((seg == 1) ? src1 : src2);
    const void* dst = (seg == 0) ? dst0 : ((seg == 1) ? dst1 : dst2);
    int s, d;
    if (g_is64) {
        s = (int)((const long long*)src)[e];
        d = (int)((const long long*)dst)[e];
    } else {
        s = ((const int*)src)[e];
        d = ((const int*)dst)[e];
    }
    if ((unsigned)s >= NN || (unsigned)d >= NN) return;
    int idx  = seg * NN + d;
    int base = g_off[idx] + g_bsumx[idx >> 8];
    int pos  = base + atomicAdd(&g_cur[idx], 1);
    g_csr[pos] = s;
}

// ================= phase 2: fused fp16 gather + mean -> fp16 A =================
__global__ __launch_bounds__(256) void node_gather_kernel()
{
    int gw = (blockIdx.x * blockDim.x + threadIdx.x) >> 5;
    if (gw >= NSEG3) return;
    const int lane = threadIdx.x & 31;
    const int seg  = gw / NN;
    const int node = gw - seg * NN;

    const int deg  = g_icnt[gw];
    const int base = g_off[gw] + g_bsumx[gw >> 8];

    float a[8];
#pragma unroll
    for (int i = 0; i < 8; i++) a[i] = 0.f;

    int p = 0;
    for (; p + 3 < deg; p += 4) {            // 4 rows in flight -> MLP 4
        int s0 = g_csr[base + p];
        int s1 = g_csr[base + p + 1];
        int s2 = g_csr[base + p + 2];
        int s3 = g_csr[base + p + 3];
        uint4 q0 = __ldg(&reinterpret_cast<const uint4*>(g_fh + (size_t)s0 * DD)[lane]);
        uint4 q1 = __ldg(&reinterpret_cast<const uint4*>(g_fh + (size_t)s1 * DD)[lane]);
        uint4 q2 = __ldg(&reinterpret_cast<const uint4*>(g_fh + (size_t)s2 * DD)[lane]);
        uint4 q3 = __ldg(&reinterpret_cast<const uint4*>(g_fh + (size_t)s3 * DD)[lane]);
        acc8_from_u4(a, q0);
        acc8_from_u4(a, q1);
        acc8_from_u4(a, q2);
        acc8_from_u4(a, q3);
    }
    for (; p < deg; p++) {
        int s0 = g_csr[base + p];
        uint4 q0 = __ldg(&reinterpret_cast<const uint4*>(g_fh + (size_t)s0 * DD)[lane]);
        acc8_from_u4(a, q0);
    }

    const float inv = (deg > 0) ? (1.f / (float)deg) : 0.f;
    __half2 p0 = __floats2half2_rn(a[0] * inv, a[1] * inv);
    __half2 p1 = __floats2half2_rn(a[2] * inv, a[3] * inv);
    __half2 p2 = __floats2half2_rn(a[4] * inv, a[5] * inv);
    __half2 p3 = __floats2half2_rn(a[6] * inv, a[7] * inv);
    uint4 Q;
    Q.x = *reinterpret_cast<uint32_t*>(&p0);
    Q.y = *reinterpret_cast<uint32_t*>(&p1);
    Q.z = *reinterpret_cast<uint32_t*>(&p2);
    Q.w = *reinterpret_cast<uint32_t*>(&p3);
    unsigned short* ra = g_a + (size_t)node * KTOT + seg * DD;
    *reinterpret_cast<uint4*>(ra + 8 * lane) = Q;
    if (lane == 0)
        g_flg[gw] = (deg > 0) ? 1.f : 0.f;
}

// ================= phase 2b: B transpose -> fp16 =================
__global__ void convertB_kernel(const float* __restrict__ W0,
                                const float* __restrict__ W1,
                                const float* __restrict__ W2) {
    __shared__ float tile[32][33];
    const int seg = blockIdx.z;
    const float* W = (seg == 0) ? W0 : ((seg == 1) ? W1 : W2);
    const int kb = blockIdx.x * 32, nb = blockIdx.y * 32;
    const int tx = threadIdx.x, ty = threadIdx.y;
#pragma unroll
    for (int i = 0; i < 32; i += 8)
        tile[ty + i][tx] = W[(size_t)(kb + ty + i) * DD + nb + tx];
    __syncthreads();
#pragma unroll
    for (int i = 0; i < 32; i += 8) {
        int n = nb + ty + i, k = kb + tx;
        __half h = __float2half_rn(tile[tx][ty + i]);
        g_b[(size_t)n * KTOT + seg * DD + k] = *reinterpret_cast<unsigned short*>(&h);
    }
}

// ================= phase 3: mma.sync fp16 GEMM, single pass (A*B) =================
// CTA 128(M) x 256(N), BK=64. Warp tile 64x64, 8 warps 2x4.
// Stage: A(16K) B(32K) = 48KB; 3 stages = 144KB.
#define O_A  0
#define O_B  16384
#define STG_SZ 49152
#define NSTAGE 3
#define NCHUNK 12
#define SMEM_GEMM (NSTAGE * STG_SZ)

__device__ __forceinline__ void load_chunk(int kc, uint32_t stg, int t, int m0) {
    const char* ag = (const char*)g_a + ((size_t)m0 * KTOT + kc * 64) * 2;
    const char* bg = (const char*)g_b + ((size_t)kc * 64) * 2;
#pragma unroll
    for (int i = t; i < 1024; i += 256) {      // A: 128 rows x 128B
        int r = i >> 3, j = (i & 7) * 16;
        cp16(stg + O_A + sw128(r * 128 + j), ag + (size_t)r * (KTOT * 2) + j);
    }
#pragma unroll
    for (int i = t; i < 2048; i += 256) {      // B: 256 rows x 128B
        int r = i >> 3, j = (i & 7) * 16;
        cp16(stg + O_B + sw128(r * 128 + j), bg + (size_t)r * (KTOT * 2) + j);
    }
    asm volatile("cp.async.commit_group;" ::: "memory");
}

__global__ __launch_bounds__(256) void gemm_mma_kernel(
    const float* __restrict__ b0, const float* __restrict__ b1,
    const float* __restrict__ b2, float* __restrict__ out)
{
    extern __shared__ char smem[];
    const uint32_t sb = smem_u32(smem);
    const int t = threadIdx.x, wid = t >> 5, lane = t & 31;
    const int m0 = blockIdx.x * 128;
    const int wm = wid & 1, wn = wid >> 1;

    float acc[4][8][4];
#pragma unroll
    for (int i = 0; i < 4; i++)
#pragma unroll
        for (int j = 0; j < 8; j++)
#pragma unroll
            for (int k = 0; k < 4; k++) acc[i][j][k] = 0.f;

    load_chunk(0, sb, t, m0);
    load_chunk(1, sb + STG_SZ, t, m0);

    const uint32_t arow  = (uint32_t)(wm * 64 + (lane & 15));
    const uint32_t acol8 = (uint32_t)(lane >> 4);
    const uint32_t brow  = (uint32_t)(wn * 64 + (lane & 7) + ((lane >> 4) & 1) * 8);
    const uint32_t bcol8 = (uint32_t)((lane >> 3) & 1);

#pragma unroll 1
    for (int c = 0; c < NCHUNK; c++) {
        const uint32_t stg = sb + (uint32_t)(c % NSTAGE) * STG_SZ;

        asm volatile("cp.async.wait_group 1;" ::: "memory");
        __syncthreads();

        if (c + 2 < NCHUNK)
            load_chunk(c + 2, sb + (uint32_t)((c + 2) % NSTAGE) * STG_SZ, t, m0);

#pragma unroll
        for (int ks = 0; ks < 4; ks++) {
            uint32_t av[4][4];
#pragma unroll
            for (int mf = 0; mf < 4; mf++) {
                uint32_t off = sw128((arow + mf * 16) * 128 + (ks * 16 + acol8 * 8) * 2);
                ldm4(av[mf], stg + O_A + off);
            }
#pragma unroll
            for (int nf2 = 0; nf2 < 4; nf2++) {
                uint32_t bv[4];
                uint32_t off = sw128((brow + nf2 * 16) * 128 + (ks * 16 + bcol8 * 8) * 2);
                ldm4(bv, stg + O_B + off);
#pragma unroll
                for (int mf = 0; mf < 4; mf++)
#pragma unroll
                    for (int j = 0; j < 2; j++)
                        mma_f16(acc[mf][nf2 * 2 + j], av[mf], &bv[2 * j]);
            }
        }
    }

    const int gid = lane >> 2, t4 = lane & 3;
    float2 bb0[8], bb1[8], bb2[8];
#pragma unroll
    for (int nf = 0; nf < 8; nf++) {
        int col = wn * 64 + nf * 8 + t4 * 2;
        bb0[nf] = *reinterpret_cast<const float2*>(b0 + col);
        bb1[nf] = *reinterpret_cast<const float2*>(b1 + col);
        bb2[nf] = *reinterpret_cast<const float2*>(b2 + col);
    }
#pragma unroll
    for (int mf = 0; mf < 4; mf++) {
#pragma unroll
        for (int half = 0; half < 2; half++) {
            int row = m0 + wm * 64 + mf * 16 + gid + half * 8;
            if (row >= NN) continue;
            float f0 = g_flg[row], f1 = g_flg[NN + row], f2 = g_flg[2 * NN + row];
#pragma unroll
            for (int nf = 0; nf < 8; nf++) {
                int col = wn * 64 + nf * 8 + t4 * 2;
                float2 o;
                o.x = fmaxf(acc[mf][nf][2 * half]     + f0 * bb0[nf].x + f1 * bb1[nf].x + f2 * bb2[nf].x, 0.f);
                o.y = fmaxf(acc[mf][nf][2 * half + 1] + f0 * bb0[nf].y + f1 * bb1[nf].y + f2 * bb2[nf].y, 0.f);
                *reinterpret_cast<float2*>(out + (size_t)row * DD + col) = o;
            }
        }
    }
}

// ================= launch =================
extern "C" void kernel_launch(void* const* d_in, const int* in_sizes, int n_in,
                              void* d_out, int out_size)
{
    const float* features = (const float*)d_in[0];
    const void*  src0 = d_in[1]; const void* dst0 = d_in[2];
    const void*  src1 = d_in[3]; const void* dst1 = d_in[4];
    const void*  src2 = d_in[5]; const void* dst2 = d_in[6];
    const float* W0 = (const float*)d_in[7];  const float* b0 = (const float*)d_in[8];
    const float* W1 = (const float*)d_in[9];  const float* b1 = (const float*)d_in[10];
    const float* W2 = (const float*)d_in[11]; const float* b2 = (const float*)d_in[12];
    float* out = (float*)d_out;

    cudaFuncSetAttribute(gemm_mma_kernel, cudaFuncAttributeMaxDynamicSharedMemorySize,
                         SMEM_GEMM);

    const int nScanBlocks = (NSEG3 + 255) / 256;   // 586

    zero_detect_kernel<<<nScanBlocks, 256>>>((const int*)src0);
    {
        size_t total = (size_t)NN * DD / 8;
        convertF_kernel<<<(int)((total + 255) / 256), 256>>>(features);
    }
    {
        dim3 grid((EE + 255) / 256, 1, 3);
        hist_kernel<<<grid, 256>>>(dst0, dst1, dst2);
    }
    scan1_kernel<<<nScanBlocks, 256>>>();
    scan2_kernel<<<1, 1024>>>(nScanBlocks);
    {
        dim3 grid((EE + 255) / 256, 1, 3);
        scatter_kernel<<<grid, 256>>>(src0, dst0, src1, dst1, src2, dst2);
    }
    {
        int blocks = (NSEG3 * 32 + 255) / 256;
        node_gather_kernel<<<blocks, 256>>>();
    }
    {
        dim3 grid(DD / 32, DD / 32, 3);
        convertB_kernel<<<grid, dim3(32, 8)>>>(W0, W1, W2);
    }
    {
        dim3 grid(MPAD / 128, 1);
        gemm_mma_kernel<<<grid, 256, SMEM_GEMM>>>(b0, b1, b2, out);
    }
}

// round 12
// speedup vs baseline: 2.4083x; 1.0323x over previous
#include <cuda_runtime.h>
#include <cuda_bf16.h>
#include <cuda_fp16.h>
#include <cstdint>

#define NN   50000
#define EE   500000
#define DD   256
#define KTOT 768            // 3 * DD
#define MPAD 50048          // 391 * 128
#define NSEG3 (3 * NN)

// ---------------- scratch (static device globals; zero-initialized at load) ----------------
__device__ int            g_is64;
__device__ int            g_total;                   // CSR allocation cursor
__device__ int            g_icnt[NSEG3];
__device__ int            g_cur[NSEG3];
__device__ int            g_off[NSEG3];              // ABSOLUTE csr offsets
__device__ int            g_csr[3 * EE];
__device__ float          g_flg[NSEG3];
__device__ unsigned short g_fh[(size_t)NN * DD];     // fp16 copy of features
__device__ unsigned short g_a [(size_t)MPAD * KTOT]; // fp16 mean-agg A (rows>=NN stay 0)
__device__ unsigned short g_b [(size_t)DD * KTOT];   // B[n][k] = W_seg[k][n], fp16

// ================= helpers =================
__device__ __forceinline__ uint32_t smem_u32(const void* p) {
    uint32_t a;
    asm("{ .reg .u64 t; cvta.to.shared.u64 t, %1; cvt.u32.u64 %0, t; }" : "=r"(a) : "l"(p));
    return a;
}
__device__ __forceinline__ uint32_t sw128(uint32_t b) { return b ^ ((b >> 3) & 0x70); }

__device__ __forceinline__ void cp16(uint32_t dst, const void* src) {
    asm volatile("cp.async.cg.shared.global [%0], [%1], 16;" :: "r"(dst), "l"(src));
}
__device__ __forceinline__ void ldm4(uint32_t* r, uint32_t addr) {
    asm volatile("ldmatrix.sync.aligned.m8n8.x4.shared.b16 {%0,%1,%2,%3}, [%4];"
                 : "=r"(r[0]), "=r"(r[1]), "=r"(r[2]), "=r"(r[3]) : "r"(addr));
}
__device__ __forceinline__ void mma_f16(float* c, const uint32_t* a, const uint32_t* b) {
    asm volatile("mma.sync.aligned.m16n8k16.row.col.f32.f16.f16.f32 "
                 "{%0,%1,%2,%3}, {%4,%5,%6,%7}, {%8,%9}, {%0,%1,%2,%3};"
                 : "+f"(c[0]), "+f"(c[1]), "+f"(c[2]), "+f"(c[3])
                 : "r"(a[0]), "r"(a[1]), "r"(a[2]), "r"(a[3]), "r"(b[0]), "r"(b[1]));
}
__device__ __forceinline__ void acc8_from_u4(float* a, uint4 q) {
    __half2 p0 = *reinterpret_cast<__half2*>(&q.x);
    __half2 p1 = *reinterpret_cast<__half2*>(&q.y);
    __half2 p2 = *reinterpret_cast<__half2*>(&q.z);
    __half2 p3 = *reinterpret_cast<__half2*>(&q.w);
    float2 f0 = __half22float2(p0);
    float2 f1 = __half22float2(p1);
    float2 f2 = __half22float2(p2);
    float2 f3 = __half22float2(p3);
    a[0] += f0.x; a[1] += f0.y; a[2] += f1.x; a[3] += f1.y;
    a[4] += f2.x; a[5] += f2.y; a[6] += f3.x; a[7] += f3.y;
}

// ================= K1: fused zero + detect + convertF + convertB =================
// block ranges: [0, ZB) zero, [ZB, ZB+FB) convertF, [ZB+FB, ZB+FB+BB) convertB
#define ZB 586
#define FB 6250        // (NN*DD/8) / 256
#define BB 192         // 8 * 8 * 3

__global__ __launch_bounds__(256) void init_kernel(
    const int* __restrict__ src_detect,
    const float* __restrict__ feat,
    const float* __restrict__ W0, const float* __restrict__ W1,
    const float* __restrict__ W2)
{
    const int b = blockIdx.x;
    if (b < ZB) {
        int i = b * 256 + threadIdx.x;
        if (i < NSEG3) { g_icnt[i] = 0; g_cur[i] = 0; }
        if (i == 0) {
            g_total = 0;
            int ok = 1;
#pragma unroll
            for (int k = 0; k < 32; k++)
                if (src_detect[2 * k + 1] != 0) ok = 0;
            g_is64 = ok;
        }
        return;
    }
    if (b < ZB + FB) {
        size_t i = (size_t)(b - ZB) * 256 + threadIdx.x;
        const size_t total = (size_t)NN * DD / 8;
        if (i >= total) return;
        float4 v0 = reinterpret_cast<const float4*>(feat)[2 * i];
        float4 v1 = reinterpret_cast<const float4*>(feat)[2 * i + 1];
        __half2 p0 = __floats2half2_rn(v0.x, v0.y);
        __half2 p1 = __floats2half2_rn(v0.z, v0.w);
        __half2 p2 = __floats2half2_rn(v1.x, v1.y);
        __half2 p3 = __floats2half2_rn(v1.z, v1.w);
        uint4 q;
        q.x = *reinterpret_cast<uint32_t*>(&p0);
        q.y = *reinterpret_cast<uint32_t*>(&p1);
        q.z = *reinterpret_cast<uint32_t*>(&p2);
        q.w = *reinterpret_cast<uint32_t*>(&p3);
        reinterpret_cast<uint4*>(g_fh)[i] = q;
        return;
    }
    // convertB: 192 blocks = (kb 0..7) x (nb 0..7) x (seg 0..2)
    {
        __shared__ float tile[32][33];
        int cb = b - ZB - FB;
        const int seg = cb / 64;
        const int rem = cb % 64;
        const int kb = (rem / 8) * 32, nb = (rem % 8) * 32;
        const float* W = (seg == 0) ? W0 : ((seg == 1) ? W1 : W2);
        const int tx = threadIdx.x & 31, ty = threadIdx.x >> 5;   // 32 x 8
#pragma unroll
        for (int i = 0; i < 32; i += 8)
            tile[ty + i][tx] = W[(size_t)(kb + ty + i) * DD + nb + tx];
        __syncthreads();
#pragma unroll
        for (int i = 0; i < 32; i += 8) {
            int n = nb + ty + i, k = kb + tx;
            __half h = __float2half_rn(tile[tx][ty + i]);
            g_b[(size_t)n * KTOT + seg * DD + k] = *reinterpret_cast<unsigned short*>(&h);
        }
    }
}

// ================= K2: histogram =================
__global__ __launch_bounds__(256) void hist_kernel(
    const void* __restrict__ dst0, const void* __restrict__ dst1,
    const void* __restrict__ dst2)
{
    int e = blockIdx.x * blockDim.x + threadIdx.x;
    if (e >= EE) return;
    const int seg = blockIdx.z;
    const void* dst = (seg == 0) ? dst0 : ((seg == 1) ? dst1 : dst2);
    int d = g_is64 ? (int)((const long long*)dst)[e] : ((const int*)dst)[e];
    if ((unsigned)d >= NN) return;
    atomicAdd(&g_icnt[seg * NN + d], 1);
}

// ================= K3: block scan + atomic base allocation -> absolute g_off =================
__global__ __launch_bounds__(256) void allocscan_kernel() {
    __shared__ int sh[256];
    __shared__ int s_base;
    int t = threadIdx.x;
    int i = blockIdx.x * 256 + t;
    int v = (i < NSEG3) ? g_icnt[i] : 0;
    sh[t] = v;
    __syncthreads();
    int acc = v;
#pragma unroll
    for (int ofs = 1; ofs < 256; ofs <<= 1) {
        int o = (t >= ofs) ? sh[t - ofs] : 0;
        __syncthreads();
        acc += o;
        sh[t] = acc;
        __syncthreads();
    }
    if (t == 255) s_base = atomicAdd(&g_total, acc);   // per-block CSR range (order irrelevant)
    __syncthreads();
    if (i < NSEG3) g_off[i] = s_base + acc - v;        // absolute exclusive offset
}

// ================= K4: scatter =================
__global__ __launch_bounds__(256) void scatter_kernel(
    const void* __restrict__ src0, const void* __restrict__ dst0,
    const void* __restrict__ src1, const void* __restrict__ dst1,
    const void* __restrict__ src2, const void* __restrict__ dst2)
{
    int e = blockIdx.x * blockDim.x + threadIdx.x;
    if (e >= EE) return;
    const int seg = blockIdx.z;
    const void* src = (seg == 0) ? src0 : ((seg == 1) ? src1 : src2);
    const void* dst = (seg == 0) ? dst0 : ((seg == 1) ? dst1 : dst2);
    int s, d;
    if (g_is64) {
        s = (int)((const long long*)src)[e];
        d = (int)((const long long*)dst)[e];
    } else {
        s = ((const int*)src)[e];
        d = ((const int*)dst)[e];
    }
    if ((unsigned)s >= NN || (unsigned)d >= NN) return;
    int idx = seg * NN + d;
    int pos = g_off[idx] + atomicAdd(&g_cur[idx], 1);
    g_csr[pos] = s;
}

// ================= K5: fused fp16 gather + mean -> fp16 A =================
__global__ __launch_bounds__(256) void node_gather_kernel()
{
    int gw = (blockIdx.x * blockDim.x + threadIdx.x) >> 5;
    if (gw >= NSEG3) return;
    const int lane = threadIdx.x & 31;
    const int seg  = gw / NN;
    const int node = gw - seg * NN;

    const int deg  = g_icnt[gw];
    const int base = g_off[gw];

    float a[8];
#pragma unroll
    for (int i = 0; i < 8; i++) a[i] = 0.f;

    int p = 0;
    for (; p + 3 < deg; p += 4) {            // 4 rows in flight -> MLP 4
        int s0 = g_csr[base + p];
        int s1 = g_csr[base + p + 1];
        int s2 = g_csr[base + p + 2];
        int s3 = g_csr[base + p + 3];
        uint4 q0 = __ldg(&reinterpret_cast<const uint4*>(g_fh + (size_t)s0 * DD)[lane]);
        uint4 q1 = __ldg(&reinterpret_cast<const uint4*>(g_fh + (size_t)s1 * DD)[lane]);
        uint4 q2 = __ldg(&reinterpret_cast<const uint4*>(g_fh + (size_t)s2 * DD)[lane]);
        uint4 q3 = __ldg(&reinterpret_cast<const uint4*>(g_fh + (size_t)s3 * DD)[lane]);
        acc8_from_u4(a, q0);
        acc8_from_u4(a, q1);
        acc8_from_u4(a, q2);
        acc8_from_u4(a, q3);
    }
    for (; p < deg; p++) {
        int s0 = g_csr[base + p];
        uint4 q0 = __ldg(&reinterpret_cast<const uint4*>(g_fh + (size_t)s0 * DD)[lane]);
        acc8_from_u4(a, q0);
    }

    const float inv = (deg > 0) ? (1.f / (float)deg) : 0.f;
    __half2 p0 = __floats2half2_rn(a[0] * inv, a[1] * inv);
    __half2 p1 = __floats2half2_rn(a[2] * inv, a[3] * inv);
    __half2 p2 = __floats2half2_rn(a[4] * inv, a[5] * inv);
    __half2 p3 = __floats2half2_rn(a[6] * inv, a[7] * inv);
    uint4 Q;
    Q.x = *reinterpret_cast<uint32_t*>(&p0);
    Q.y = *reinterpret_cast<uint32_t*>(&p1);
    Q.z = *reinterpret_cast<uint32_t*>(&p2);
    Q.w = *reinterpret_cast<uint32_t*>(&p3);
    unsigned short* ra = g_a + (size_t)node * KTOT + seg * DD;
    *reinterpret_cast<uint4*>(ra + 8 * lane) = Q;
    if (lane == 0)
        g_flg[gw] = (deg > 0) ? 1.f : 0.f;
}

// ================= K6: mma.sync fp16 GEMM, single pass (A*B) =================
// CTA 128(M) x 256(N), BK=64. Warp tile 64x64, 8 warps 2x4.
// Stage: A(16K) B(32K) = 48KB; 3 stages = 144KB.
#define O_A  0
#define O_B  16384
#define STG_SZ 49152
#define NSTAGE 3
#define NCHUNK 12
#define SMEM_GEMM (NSTAGE * STG_SZ)

__device__ __forceinline__ void load_chunk(int kc, uint32_t stg, int t, int m0) {
    const char* ag = (const char*)g_a + ((size_t)m0 * KTOT + kc * 64) * 2;
    const char* bg = (const char*)g_b + ((size_t)kc * 64) * 2;
#pragma unroll
    for (int i = t; i < 1024; i += 256) {      // A: 128 rows x 128B
        int r = i >> 3, j = (i & 7) * 16;
        cp16(stg + O_A + sw128(r * 128 + j), ag + (size_t)r * (KTOT * 2) + j);
    }
#pragma unroll
    for (int i = t; i < 2048; i += 256) {      // B: 256 rows x 128B
        int r = i >> 3, j = (i & 7) * 16;
        cp16(stg + O_B + sw128(r * 128 + j), bg + (size_t)r * (KTOT * 2) + j);
    }
    asm volatile("cp.async.commit_group;" ::: "memory");
}

__global__ __launch_bounds__(256) void gemm_mma_kernel(
    const float* __restrict__ b0, const float* __restrict__ b1,
    const float* __restrict__ b2, float* __restrict__ out)
{
    extern __shared__ char smem[];
    const uint32_t sb = smem_u32(smem);
    const int t = threadIdx.x, wid = t >> 5, lane = t & 31;
    const int m0 = blockIdx.x * 128;
    const int wm = wid & 1, wn = wid >> 1;

    float acc[4][8][4];
#pragma unroll
    for (int i = 0; i < 4; i++)
#pragma unroll
        for (int j = 0; j < 8; j++)
#pragma unroll
            for (int k = 0; k < 4; k++) acc[i][j][k] = 0.f;

    load_chunk(0, sb, t, m0);
    load_chunk(1, sb + STG_SZ, t, m0);

    const uint32_t arow  = (uint32_t)(wm * 64 + (lane & 15));
    const uint32_t acol8 = (uint32_t)(lane >> 4);
    const uint32_t brow  = (uint32_t)(wn * 64 + (lane & 7) + ((lane >> 4) & 1) * 8);
    const uint32_t bcol8 = (uint32_t)((lane >> 3) & 1);

#pragma unroll 1
    for (int c = 0; c < NCHUNK; c++) {
        const uint32_t stg = sb + (uint32_t)(c % NSTAGE) * STG_SZ;

        asm volatile("cp.async.wait_group 1;" ::: "memory");
        __syncthreads();

        if (c + 2 < NCHUNK)
            load_chunk(c + 2, sb + (uint32_t)((c + 2) % NSTAGE) * STG_SZ, t, m0);

#pragma unroll
        for (int ks = 0; ks < 4; ks++) {
            uint32_t av[4][4];
#pragma unroll
            for (int mf = 0; mf < 4; mf++) {
                uint32_t off = sw128((arow + mf * 16) * 128 + (ks * 16 + acol8 * 8) * 2);
                ldm4(av[mf], stg + O_A + off);
            }
#pragma unroll
            for (int nf2 = 0; nf2 < 4; nf2++) {
                uint32_t bv[4];
                uint32_t off = sw128((brow + nf2 * 16) * 128 + (ks * 16 + bcol8 * 8) * 2);
                ldm4(bv, stg + O_B + off);
#pragma unroll
                for (int mf = 0; mf < 4; mf++)
#pragma unroll
                    for (int j = 0; j < 2; j++)
                        mma_f16(acc[mf][nf2 * 2 + j], av[mf], &bv[2 * j]);
            }
        }
    }

    const int gid = lane >> 2, t4 = lane & 3;
    float2 bb0[8], bb1[8], bb2[8];
#pragma unroll
    for (int nf = 0; nf < 8; nf++) {
        int col = wn * 64 + nf * 8 + t4 * 2;
        bb0[nf] = *reinterpret_cast<const float2*>(b0 + col);
        bb1[nf] = *reinterpret_cast<const float2*>(b1 + col);
        bb2[nf] = *reinterpret_cast<const float2*>(b2 + col);
    }
#pragma unroll
    for (int mf = 0; mf < 4; mf++) {
#pragma unroll
        for (int half = 0; half < 2; half++) {
            int row = m0 + wm * 64 + mf * 16 + gid + half * 8;
            if (row >= NN) continue;
            float f0 = g_flg[row], f1 = g_flg[NN + row], f2 = g_flg[2 * NN + row];
#pragma unroll
            for (int nf = 0; nf < 8; nf++) {
                int col = wn * 64 + nf * 8 + t4 * 2;
                float2 o;
                o.x = fmaxf(acc[mf][nf][2 * half]     + f0 * bb0[nf].x + f1 * bb1[nf].x + f2 * bb2[nf].x, 0.f);
                o.y = fmaxf(acc[mf][nf][2 * half + 1] + f0 * bb0[nf].y + f1 * bb1[nf].y + f2 * bb2[nf].y, 0.f);
                *reinterpret_cast<float2*>(out + (size_t)row * DD + col) = o;
            }
        }
    }
}

// ================= launch =================
extern "C" void kernel_launch(void* const* d_in, const int* in_sizes, int n_in,
                              void* d_out, int out_size)
{
    const float* features = (const float*)d_in[0];
    const void*  src0 = d_in[1]; const void* dst0 = d_in[2];
    const void*  src1 = d_in[3]; const void* dst1 = d_in[4];
    const void*  src2 = d_in[5]; const void* dst2 = d_in[6];
    const float* W0 = (const float*)d_in[7];  const float* b0 = (const float*)d_in[8];
    const float* W1 = (const float*)d_in[9];  const float* b1 = (const float*)d_in[10];
    const float* W2 = (const float*)d_in[11]; const float* b2 = (const float*)d_in[12];
    float* out = (float*)d_out;

    cudaFuncSetAttribute(gemm_mma_kernel, cudaFuncAttributeMaxDynamicSharedMemorySize,
                         SMEM_GEMM);

    init_kernel<<<ZB + FB + BB, 256>>>((const int*)src0, features, W0, W1, W2);
    {
        dim3 grid((EE + 255) / 256, 1, 3);
        hist_kernel<<<grid, 256>>>(dst0, dst1, dst2);
    }
    allocscan_kernel<<<(NSEG3 + 255) / 256, 256>>>();
    {
        dim3 grid((EE + 255) / 256, 1, 3);
        scatter_kernel<<<grid, 256>>>(src0, dst0, src1, dst1, src2, dst2);
    }
    {
        int blocks = (NSEG3 * 32 + 255) / 256;
        node_gather_kernel<<<blocks, 256>>>();
    }
    {
        dim3 grid(MPAD / 128, 1);
        gemm_mma_kernel<<<grid, 256, SMEM_GEMM>>>(b0, b1, b2, out);
    }
}

// round 13
// speedup vs baseline: 2.6235x; 1.0893x over previous
#include <cuda_runtime.h>
#include <cuda_bf16.h>
#include <cuda_fp16.h>
#include <cstdint>

#define NN   50000
#define EE   500000
#define DD   256
#define KTOT 768            // 3 * DD
#define MPAD 50048          // 391 * 128
#define NSEG3 (3 * NN)
#define CAP  64             // bucket capacity; P(Poisson(10) >= 64) ~ 4e-18

// ---------------- scratch (static device globals; zero-initialized at load) ----------------
__device__ int            g_is64;
__device__ int            g_cur[NSEG3];               // per-(seg,node) degree / cursor
__device__ int            g_bkt[(size_t)NSEG3 * CAP]; // bucketed src indices (38.4 MB)
__device__ float          g_flg[NSEG3];
__device__ unsigned short g_fh[(size_t)NN * DD];      // fp16 copy of features
__device__ unsigned short g_a [(size_t)MPAD * KTOT];  // fp16 mean-agg A (rows>=NN stay 0)
__device__ unsigned short g_b [(size_t)DD * KTOT];    // B[n][k] = W_seg[k][n], fp16

// ================= helpers =================
__device__ __forceinline__ uint32_t smem_u32(const void* p) {
    uint32_t a;
    asm("{ .reg .u64 t; cvta.to.shared.u64 t, %1; cvt.u32.u64 %0, t; }" : "=r"(a) : "l"(p));
    return a;
}
__device__ __forceinline__ uint32_t sw128(uint32_t b) { return b ^ ((b >> 3) & 0x70); }

__device__ __forceinline__ void cp16(uint32_t dst, const void* src) {
    asm volatile("cp.async.cg.shared.global [%0], [%1], 16;" :: "r"(dst), "l"(src));
}
__device__ __forceinline__ void ldm4(uint32_t* r, uint32_t addr) {
    asm volatile("ldmatrix.sync.aligned.m8n8.x4.shared.b16 {%0,%1,%2,%3}, [%4];"
                 : "=r"(r[0]), "=r"(r[1]), "=r"(r[2]), "=r"(r[3]) : "r"(addr));
}
__device__ __forceinline__ void mma_f16(float* c, const uint32_t* a, const uint32_t* b) {
    asm volatile("mma.sync.aligned.m16n8k16.row.col.f32.f16.f16.f32 "
                 "{%0,%1,%2,%3}, {%4,%5,%6,%7}, {%8,%9}, {%0,%1,%2,%3};"
                 : "+f"(c[0]), "+f"(c[1]), "+f"(c[2]), "+f"(c[3])
                 : "r"(a[0]), "r"(a[1]), "r"(a[2]), "r"(a[3]), "r"(b[0]), "r"(b[1]));
}
__device__ __forceinline__ void acc8_from_u4(float* a, uint4 q) {
    __half2 p0 = *reinterpret_cast<__half2*>(&q.x);
    __half2 p1 = *reinterpret_cast<__half2*>(&q.y);
    __half2 p2 = *reinterpret_cast<__half2*>(&q.z);
    __half2 p3 = *reinterpret_cast<__half2*>(&q.w);
    float2 f0 = __half22float2(p0);
    float2 f1 = __half22float2(p1);
    float2 f2 = __half22float2(p2);
    float2 f3 = __half22float2(p3);
    a[0] += f0.x; a[1] += f0.y; a[2] += f1.x; a[3] += f1.y;
    a[4] += f2.x; a[5] += f2.y; a[6] += f3.x; a[7] += f3.y;
}

// ================= K1: fused zero + detect + convertF + convertB =================
// block ranges: [0, ZB) zero, [ZB, ZB+FB) convertF, [ZB+FB, ZB+FB+BB) convertB
#define ZB 586
#define FB 6250        // (NN*DD/8) / 256
#define BB 192         // 8 * 8 * 3

__global__ __launch_bounds__(256) void init_kernel(
    const int* __restrict__ src_detect,
    const float* __restrict__ feat,
    const float* __restrict__ W0, const float* __restrict__ W1,
    const float* __restrict__ W2)
{
    const int b = blockIdx.x;
    if (b < ZB) {
        int i = b * 256 + threadIdx.x;
        if (i < NSEG3) g_cur[i] = 0;
        if (i == 0) {
            int ok = 1;
#pragma unroll
            for (int k = 0; k < 32; k++)
                if (src_detect[2 * k + 1] != 0) ok = 0;
            g_is64 = ok;
        }
        return;
    }
    if (b < ZB + FB) {
        size_t i = (size_t)(b - ZB) * 256 + threadIdx.x;
        const size_t total = (size_t)NN * DD / 8;
        if (i >= total) return;
        float4 v0 = reinterpret_cast<const float4*>(feat)[2 * i];
        float4 v1 = reinterpret_cast<const float4*>(feat)[2 * i + 1];
        __half2 p0 = __floats2half2_rn(v0.x, v0.y);
        __half2 p1 = __floats2half2_rn(v0.z, v0.w);
        __half2 p2 = __floats2half2_rn(v1.x, v1.y);
        __half2 p3 = __floats2half2_rn(v1.z, v1.w);
        uint4 q;
        q.x = *reinterpret_cast<uint32_t*>(&p0);
        q.y = *reinterpret_cast<uint32_t*>(&p1);
        q.z = *reinterpret_cast<uint32_t*>(&p2);
        q.w = *reinterpret_cast<uint32_t*>(&p3);
        reinterpret_cast<uint4*>(g_fh)[i] = q;
        return;
    }
    // convertB: 192 blocks = (kb 0..7) x (nb 0..7) x (seg 0..2)
    {
        __shared__ float tile[32][33];
        int cb = b - ZB - FB;
        const int seg = cb / 64;
        const int rem = cb % 64;
        const int kb = (rem / 8) * 32, nb = (rem % 8) * 32;
        const float* W = (seg == 0) ? W0 : ((seg == 1) ? W1 : W2);
        const int tx = threadIdx.x & 31, ty = threadIdx.x >> 5;   // 32 x 8
#pragma unroll
        for (int i = 0; i < 32; i += 8)
            tile[ty + i][tx] = W[(size_t)(kb + ty + i) * DD + nb + tx];
        __syncthreads();
#pragma unroll
        for (int i = 0; i < 32; i += 8) {
            int n = nb + ty + i, k = kb + tx;
            __half h = __float2half_rn(tile[tx][ty + i]);
            g_b[(size_t)n * KTOT + seg * DD + k] = *reinterpret_cast<unsigned short*>(&h);
        }
    }
}

// ================= K2: single-pass edge bucketing =================
__global__ __launch_bounds__(256) void bucket_kernel(
    const void* __restrict__ src0, const void* __restrict__ dst0,
    const void* __restrict__ src1, const void* __restrict__ dst1,
    const void* __restrict__ src2, const void* __restrict__ dst2)
{
    int e = blockIdx.x * blockDim.x + threadIdx.x;
    if (e >= EE) return;
    const int seg = blockIdx.z;
    const void* src = (seg == 0) ? src0 : ((seg == 1) ? src1 : src2);
    const void* dst = (seg == 0) ? dst0 : ((seg == 1) ? dst1 : dst2);
    int s, d;
    if (g_is64) {
        s = (int)((const long long*)src)[e];
        d = (int)((const long long*)dst)[e];
    } else {
        s = ((const int*)src)[e];
        d = ((const int*)dst)[e];
    }
    if ((unsigned)s >= NN || (unsigned)d >= NN) return;
    int idx  = seg * NN + d;
    int slot = atomicAdd(&g_cur[idx], 1);
    if (slot < CAP)                                   // overflow guard (P ~ 1e-12)
        g_bkt[(size_t)idx * CAP + slot] = s;
}

// ================= K3: fused fp16 gather + mean -> fp16 A =================
__global__ __launch_bounds__(256) void node_gather_kernel()
{
    int gw = (blockIdx.x * blockDim.x + threadIdx.x) >> 5;
    if (gw >= NSEG3) return;
    const int lane = threadIdx.x & 31;
    const int seg  = gw / NN;
    const int node = gw - seg * NN;

    const int deg = g_cur[gw];
    const int dn  = (deg < CAP) ? deg : CAP;
    const int* __restrict__ bkt = g_bkt + (size_t)gw * CAP;

    float a[8];
#pragma unroll
    for (int i = 0; i < 8; i++) a[i] = 0.f;

    int p = 0;
    for (; p + 3 < dn; p += 4) {            // 4 rows in flight -> MLP 4
        int s0 = bkt[p];
        int s1 = bkt[p + 1];
        int s2 = bkt[p + 2];
        int s3 = bkt[p + 3];
        uint4 q0 = __ldg(&reinterpret_cast<const uint4*>(g_fh + (size_t)s0 * DD)[lane]);
        uint4 q1 = __ldg(&reinterpret_cast<const uint4*>(g_fh + (size_t)s1 * DD)[lane]);
        uint4 q2 = __ldg(&reinterpret_cast<const uint4*>(g_fh + (size_t)s2 * DD)[lane]);
        uint4 q3 = __ldg(&reinterpret_cast<const uint4*>(g_fh + (size_t)s3 * DD)[lane]);
        acc8_from_u4(a, q0);
        acc8_from_u4(a, q1);
        acc8_from_u4(a, q2);
        acc8_from_u4(a, q3);
    }
    for (; p < dn; p++) {
        int s0 = bkt[p];
        uint4 q0 = __ldg(&reinterpret_cast<const uint4*>(g_fh + (size_t)s0 * DD)[lane]);
        acc8_from_u4(a, q0);
    }

    const float inv = (deg > 0) ? (1.f / (float)deg) : 0.f;
    __half2 p0 = __floats2half2_rn(a[0] * inv, a[1] * inv);
    __half2 p1 = __floats2half2_rn(a[2] * inv, a[3] * inv);
    __half2 p2 = __floats2half2_rn(a[4] * inv, a[5] * inv);
    __half2 p3 = __floats2half2_rn(a[6] * inv, a[7] * inv);
    uint4 Q;
    Q.x = *reinterpret_cast<uint32_t*>(&p0);
    Q.y = *reinterpret_cast<uint32_t*>(&p1);
    Q.z = *reinterpret_cast<uint32_t*>(&p2);
    Q.w = *reinterpret_cast<uint32_t*>(&p3);
    unsigned short* ra = g_a + (size_t)node * KTOT + seg * DD;
    *reinterpret_cast<uint4*>(ra + 8 * lane) = Q;
    if (lane == 0)
        g_flg[gw] = (deg > 0) ? 1.f : 0.f;
}

// ================= K4: mma.sync fp16 GEMM, single pass (A*B) =================
// CTA 128(M) x 256(N), BK=64. Warp tile 64x64, 8 warps 2x4.
// Stage: A(16K) B(32K) = 48KB; 3 stages = 144KB.
#define O_A  0
#define O_B  16384
#define STG_SZ 49152
#define NSTAGE 3
#define NCHUNK 12
#define SMEM_GEMM (NSTAGE * STG_SZ)

__device__ __forceinline__ void load_chunk(int kc, uint32_t stg, int t, int m0) {
    const char* ag = (const char*)g_a + ((size_t)m0 * KTOT + kc * 64) * 2;
    const char* bg = (const char*)g_b + ((size_t)kc * 64) * 2;
#pragma unroll
    for (int i = t; i < 1024; i += 256) {      // A: 128 rows x 128B
        int r = i >> 3, j = (i & 7) * 16;
        cp16(stg + O_A + sw128(r * 128 + j), ag + (size_t)r * (KTOT * 2) + j);
    }
#pragma unroll
    for (int i = t; i < 2048; i += 256) {      // B: 256 rows x 128B
        int r = i >> 3, j = (i & 7) * 16;
        cp16(stg + O_B + sw128(r * 128 + j), bg + (size_t)r * (KTOT * 2) + j);
    }
    asm volatile("cp.async.commit_group;" ::: "memory");
}

__global__ __launch_bounds__(256) void gemm_mma_kernel(
    const float* __restrict__ b0, const float* __restrict__ b1,
    const float* __restrict__ b2, float* __restrict__ out)
{
    extern __shared__ char smem[];
    const uint32_t sb = smem_u32(smem);
    const int t = threadIdx.x, wid = t >> 5, lane = t & 31;
    const int m0 = blockIdx.x * 128;
    const int wm = wid & 1, wn = wid >> 1;

    float acc[4][8][4];
#pragma unroll
    for (int i = 0; i < 4; i++)
#pragma unroll
        for (int j = 0; j < 8; j++)
#pragma unroll
            for (int k = 0; k < 4; k++) acc[i][j][k] = 0.f;

    load_chunk(0, sb, t, m0);
    load_chunk(1, sb + STG_SZ, t, m0);

    const uint32_t arow  = (uint32_t)(wm * 64 + (lane & 15));
    const uint32_t acol8 = (uint32_t)(lane >> 4);
    const uint32_t brow  = (uint32_t)(wn * 64 + (lane & 7) + ((lane >> 4) & 1) * 8);
    const uint32_t bcol8 = (uint32_t)((lane >> 3) & 1);

#pragma unroll 1
    for (int c = 0; c < NCHUNK; c++) {
        const uint32_t stg = sb + (uint32_t)(c % NSTAGE) * STG_SZ;

        asm volatile("cp.async.wait_group 1;" ::: "memory");
        __syncthreads();

        if (c + 2 < NCHUNK)
            load_chunk(c + 2, sb + (uint32_t)((c + 2) % NSTAGE) * STG_SZ, t, m0);

#pragma unroll
        for (int ks = 0; ks < 4; ks++) {
            uint32_t av[4][4];
#pragma unroll
            for (int mf = 0; mf < 4; mf++) {
                uint32_t off = sw128((arow + mf * 16) * 128 + (ks * 16 + acol8 * 8) * 2);
                ldm4(av[mf], stg + O_A + off);
            }
#pragma unroll
            for (int nf2 = 0; nf2 < 4; nf2++) {
                uint32_t bv[4];
                uint32_t off = sw128((brow + nf2 * 16) * 128 + (ks * 16 + bcol8 * 8) * 2);
                ldm4(bv, stg + O_B + off);
#pragma unroll
                for (int mf = 0; mf < 4; mf++)
#pragma unroll
                    for (int j = 0; j < 2; j++)
                        mma_f16(acc[mf][nf2 * 2 + j], av[mf], &bv[2 * j]);
            }
        }
    }

    const int gid = lane >> 2, t4 = lane & 3;
    float2 bb0[8], bb1[8], bb2[8];
#pragma unroll
    for (int nf = 0; nf < 8; nf++) {
        int col = wn * 64 + nf * 8 + t4 * 2;
        bb0[nf] = *reinterpret_cast<const float2*>(b0 + col);
        bb1[nf] = *reinterpret_cast<const float2*>(b1 + col);
        bb2[nf] = *reinterpret_cast<const float2*>(b2 + col);
    }
#pragma unroll
    for (int mf = 0; mf < 4; mf++) {
#pragma unroll
        for (int half = 0; half < 2; half++) {
            int row = m0 + wm * 64 + mf * 16 + gid + half * 8;
            if (row >= NN) continue;
            float f0 = g_flg[row], f1 = g_flg[NN + row], f2 = g_flg[2 * NN + row];
#pragma unroll
            for (int nf = 0; nf < 8; nf++) {
                int col = wn * 64 + nf * 8 + t4 * 2;
                float2 o;
                o.x = fmaxf(acc[mf][nf][2 * half]     + f0 * bb0[nf].x + f1 * bb1[nf].x + f2 * bb2[nf].x, 0.f);
                o.y = fmaxf(acc[mf][nf][2 * half + 1] + f0 * bb0[nf].y + f1 * bb1[nf].y + f2 * bb2[nf].y, 0.f);
                *reinterpret_cast<float2*>(out + (size_t)row * DD + col) = o;
            }
        }
    }
}

// ================= launch =================
extern "C" void kernel_launch(void* const* d_in, const int* in_sizes, int n_in,
                              void* d_out, int out_size)
{
    const float* features = (const float*)d_in[0];
    const void*  src0 = d_in[1]; const void* dst0 = d_in[2];
    const void*  src1 = d_in[3]; const void* dst1 = d_in[4];
    const void*  src2 = d_in[5]; const void* dst2 = d_in[6];
    const float* W0 = (const float*)d_in[7];  const float* b0 = (const float*)d_in[8];
    const float* W1 = (const float*)d_in[9];  const float* b1 = (const float*)d_in[10];
    const float* W2 = (const float*)d_in[11]; const float* b2 = (const float*)d_in[12];
    float* out = (float*)d_out;

    cudaFuncSetAttribute(gemm_mma_kernel, cudaFuncAttributeMaxDynamicSharedMemorySize,
                         SMEM_GEMM);

    init_kernel<<<ZB + FB + BB, 256>>>((const int*)src0, features, W0, W1, W2);
    {
        dim3 grid((EE + 255) / 256, 1, 3);
        bucket_kernel<<<grid, 256>>>(src0, dst0, src1, dst1, src2, dst2);
    }
    {
        int blocks = (NSEG3 * 32 + 255) / 256;
        node_gather_kernel<<<blocks, 256>>>();
    }
    {
        dim3 grid(MPAD / 128, 1);
        gemm_mma_kernel<<<grid, 256, SMEM_GEMM>>>(b0, b1, b2, out);
    }
}

// round 16
// speedup vs baseline: 2.7639x; 1.0535x over previous
#include <cuda_runtime.h>
#include <cuda_bf16.h>
#include <cuda_fp16.h>
#include <cstdint>

#define NN   50000
#define EE   500000
#define DD   256
#define KTOT 768            // 3 * DD
#define MPAD 50048          // 391 * 128
#define NSEG3 (3 * NN)
#define CAP  64             // bucket capacity; P(Poisson(10) >= 64) ~ 4e-18

// ---------------- scratch (static device globals; zero-initialized at load) ----------------
__device__ int            g_is64;
__device__ int            g_cur[NSEG3];               // per-(seg,node) degree / cursor
__device__ int            g_bkt[(size_t)NSEG3 * CAP]; // bucketed src indices (38.4 MB)
__device__ float          g_flg[NSEG3];
__device__ unsigned short g_fh[(size_t)NN * DD];      // fp16 copy of features
__device__ unsigned short g_a [(size_t)MPAD * KTOT];  // fp16 mean-agg A (rows>=NN stay 0)
__device__ unsigned short g_b [(size_t)DD * KTOT];    // B[n][k] = W_seg[k][n], fp16

// ================= helpers =================
__device__ __forceinline__ uint32_t smem_u32(const void* p) {
    uint32_t a;
    asm("{ .reg .u64 t; cvta.to.shared.u64 t, %1; cvt.u32.u64 %0, t; }" : "=r"(a) : "l"(p));
    return a;
}
__device__ __forceinline__ uint32_t sw128(uint32_t b) { return b ^ ((b >> 3) & 0x70); }

__device__ __forceinline__ void cp16(uint32_t dst, const void* src) {
    asm volatile("cp.async.cg.shared.global [%0], [%1], 16;" :: "r"(dst), "l"(src));
}
__device__ __forceinline__ void ldm4(uint32_t* r, uint32_t addr) {
    asm volatile("ldmatrix.sync.aligned.m8n8.x4.shared.b16 {%0,%1,%2,%3}, [%4];"
                 : "=r"(r[0]), "=r"(r[1]), "=r"(r[2]), "=r"(r[3]) : "r"(addr));
}
__device__ __forceinline__ void mma_f16(float* c, const uint32_t* a, const uint32_t* b) {
    asm volatile("mma.sync.aligned.m16n8k16.row.col.f32.f16.f16.f32 "
                 "{%0,%1,%2,%3}, {%4,%5,%6,%7}, {%8,%9}, {%0,%1,%2,%3};"
                 : "+f"(c[0]), "+f"(c[1]), "+f"(c[2]), "+f"(c[3])
                 : "r"(a[0]), "r"(a[1]), "r"(a[2]), "r"(a[3]), "r"(b[0]), "r"(b[1]));
}
__device__ __forceinline__ void acc8_from_u4(float* a, uint4 q) {
    __half2 p0 = *reinterpret_cast<__half2*>(&q.x);
    __half2 p1 = *reinterpret_cast<__half2*>(&q.y);
    __half2 p2 = *reinterpret_cast<__half2*>(&q.z);
    __half2 p3 = *reinterpret_cast<__half2*>(&q.w);
    float2 f0 = __half22float2(p0);
    float2 f1 = __half22float2(p1);
    float2 f2 = __half22float2(p2);
    float2 f3 = __half22float2(p3);
    a[0] += f0.x; a[1] += f0.y; a[2] += f1.x; a[3] += f1.y;
    a[4] += f2.x; a[5] += f2.y; a[6] += f3.x; a[7] += f3.y;
}

// ================= K1: fused zero + detect + convertF + convertB =================
#define ZB 586
#define FB 6250        // (NN*DD/8) / 256
#define BB 192         // 8 * 8 * 3

__global__ __launch_bounds__(256) void init_kernel(
    const int* __restrict__ src_detect,
    const float* __restrict__ feat,
    const float* __restrict__ W0, const float* __restrict__ W1,
    const float* __restrict__ W2)
{
    const int b = blockIdx.x;
    if (b < ZB) {
        int i = b * 256 + threadIdx.x;
        if (i < NSEG3) g_cur[i] = 0;
        if (i == 0) {
            int ok = 1;
#pragma unroll
            for (int k = 0; k < 32; k++)
                if (src_detect[2 * k + 1] != 0) ok = 0;
            g_is64 = ok;
        }
        return;
    }
    if (b < ZB + FB) {
        size_t i = (size_t)(b - ZB) * 256 + threadIdx.x;
        const size_t total = (size_t)NN * DD / 8;
        if (i >= total) return;
        float4 v0 = reinterpret_cast<const float4*>(feat)[2 * i];
        float4 v1 = reinterpret_cast<const float4*>(feat)[2 * i + 1];
        __half2 p0 = __floats2half2_rn(v0.x, v0.y);
        __half2 p1 = __floats2half2_rn(v0.z, v0.w);
        __half2 p2 = __floats2half2_rn(v1.x, v1.y);
        __half2 p3 = __floats2half2_rn(v1.z, v1.w);
        uint4 q;
        q.x = *reinterpret_cast<uint32_t*>(&p0);
        q.y = *reinterpret_cast<uint32_t*>(&p1);
        q.z = *reinterpret_cast<uint32_t*>(&p2);
        q.w = *reinterpret_cast<uint32_t*>(&p3);
        reinterpret_cast<uint4*>(g_fh)[i] = q;
        return;
    }
    // convertB: 192 blocks = (kb 0..7) x (nb 0..7) x (seg 0..2)
    {
        __shared__ float tile[32][33];
        int cb = b - ZB - FB;
        const int seg = cb / 64;
        const int rem = cb % 64;
        const int kb = (rem / 8) * 32, nb = (rem % 8) * 32;
        const float* W = (seg == 0) ? W0 : ((seg == 1) ? W1 : W2);
        const int tx = threadIdx.x & 31, ty = threadIdx.x >> 5;   // 32 x 8
#pragma unroll
        for (int i = 0; i < 32; i += 8)
            tile[ty + i][tx] = W[(size_t)(kb + ty + i) * DD + nb + tx];
        __syncthreads();
#pragma unroll
        for (int i = 0; i < 32; i += 8) {
            int n = nb + ty + i, k = kb + tx;
            __half h = __float2half_rn(tile[tx][ty + i]);
            g_b[(size_t)n * KTOT + seg * DD + k] = *reinterpret_cast<unsigned short*>(&h);
        }
    }
}

// ================= K2: single-pass edge bucketing =================
__global__ __launch_bounds__(256) void bucket_kernel(
    const void* __restrict__ src0, const void* __restrict__ dst0,
    const void* __restrict__ src1, const void* __restrict__ dst1,
    const void* __restrict__ src2, const void* __restrict__ dst2)
{
    int e = blockIdx.x * blockDim.x + threadIdx.x;
    if (e >= EE) return;
    const int seg = blockIdx.z;
    const void* src = (seg == 0) ? src0 : ((seg == 1) ? src1 : src2);
    const void* dst = (seg == 0) ? dst0 : ((seg == 1) ? dst1 : dst2);
    int s, d;
    if (g_is64) {
        s = (int)((const long long*)src)[e];
        d = (int)((const long long*)dst)[e];
    } else {
        s = ((const int*)src)[e];
        d = ((const int*)dst)[e];
    }
    if ((unsigned)s >= NN || (unsigned)d >= NN) return;
    int idx  = seg * NN + d;
    int slot = atomicAdd(&g_cur[idx], 1);
    if (slot < CAP)                                   // overflow guard
        g_bkt[(size_t)idx * CAP + slot] = s;
}

// ================= K3: fused fp16 gather + mean -> fp16 A =================
__global__ __launch_bounds__(256) void node_gather_kernel()
{
    int gw = (blockIdx.x * blockDim.x + threadIdx.x) >> 5;
    if (gw >= NSEG3) return;
    const int lane = threadIdx.x & 31;
    const int seg  = gw / NN;
    const int node = gw - seg * NN;

    const int deg = g_cur[gw];
    const int dn  = (deg < CAP) ? deg : CAP;
    const int* __restrict__ bkt = g_bkt + (size_t)gw * CAP;

    float a[8];
#pragma unroll
    for (int i = 0; i < 8; i++) a[i] = 0.f;

    int p = 0;
    for (; p + 3 < dn; p += 4) {            // 4 rows in flight -> MLP 4
        int s0 = bkt[p];
        int s1 = bkt[p + 1];
        int s2 = bkt[p + 2];
        int s3 = bkt[p + 3];
        uint4 q0 = __ldg(&reinterpret_cast<const uint4*>(g_fh + (size_t)s0 * DD)[lane]);
        uint4 q1 = __ldg(&reinterpret_cast<const uint4*>(g_fh + (size_t)s1 * DD)[lane]);
        uint4 q2 = __ldg(&reinterpret_cast<const uint4*>(g_fh + (size_t)s2 * DD)[lane]);
        uint4 q3 = __ldg(&reinterpret_cast<const uint4*>(g_fh + (size_t)s3 * DD)[lane]);
        acc8_from_u4(a, q0);
        acc8_from_u4(a, q1);
        acc8_from_u4(a, q2);
        acc8_from_u4(a, q3);
    }
    for (; p < dn; p++) {
        int s0 = bkt[p];
        uint4 q0 = __ldg(&reinterpret_cast<const uint4*>(g_fh + (size_t)s0 * DD)[lane]);
        acc8_from_u4(a, q0);
    }

    const float inv = (deg > 0) ? (1.f / (float)deg) : 0.f;
    __half2 p0 = __floats2half2_rn(a[0] * inv, a[1] * inv);
    __half2 p1 = __floats2half2_rn(a[2] * inv, a[3] * inv);
    __half2 p2 = __floats2half2_rn(a[4] * inv, a[5] * inv);
    __half2 p3 = __floats2half2_rn(a[6] * inv, a[7] * inv);
    uint4 Q;
    Q.x = *reinterpret_cast<uint32_t*>(&p0);
    Q.y = *reinterpret_cast<uint32_t*>(&p1);
    Q.z = *reinterpret_cast<uint32_t*>(&p2);
    Q.w = *reinterpret_cast<uint32_t*>(&p3);
    unsigned short* ra = g_a + (size_t)node * KTOT + seg * DD;
    *reinterpret_cast<uint4*>(ra + 8 * lane) = Q;
    if (lane == 0)
        g_flg[gw] = (deg > 0) ? 1.f : 0.f;
}

// ================= K4: mma.sync fp16 GEMM, 512 threads (16 warps, 4Mx4N) =================
// CTA tile 128(M) x 256(N, full), BK=64. Warp tile 32x64. 3-stage pipeline.
// Stage: A(16K) B(32K) = 48KB; 3 stages = 144KB.
#define O_A  0
#define O_B  16384
#define STG_SZ 49152
#define NSTAGE 3
#define NCHUNK 12
#define SMEM_GEMM (NSTAGE * STG_SZ)
#define GTHREADS 512

__device__ __forceinline__ void load_chunk(int kc, uint32_t stg, int t, int m0) {
    const char* ag = (const char*)g_a + ((size_t)m0 * KTOT + kc * 64) * 2;
    const char* bg = (const char*)g_b + ((size_t)kc * 64) * 2;
#pragma unroll
    for (int i = t; i < 1024; i += GTHREADS) {   // A: 128 rows x 128B
        int r = i >> 3, j = (i & 7) * 16;
        cp16(stg + O_A + sw128(r * 128 + j), ag + (size_t)r * (KTOT * 2) + j);
    }
#pragma unroll
    for (int i = t; i < 2048; i += GTHREADS) {   // B: 256 rows x 128B
        int r = i >> 3, j = (i & 7) * 16;
        cp16(stg + O_B + sw128(r * 128 + j), bg + (size_t)r * (KTOT * 2) + j);
    }
    asm volatile("cp.async.commit_group;" ::: "memory");
}

__global__ __launch_bounds__(GTHREADS) void gemm_mma_kernel(
    const float* __restrict__ b0, const float* __restrict__ b1,
    const float* __restrict__ b2, float* __restrict__ out)
{
    extern __shared__ char smem[];
    const uint32_t sb = smem_u32(smem);
    const int t = threadIdx.x, wid = t >> 5, lane = t & 31;
    const int m0 = blockIdx.x * 128;
    const int wm = wid & 3, wn = wid >> 2;       // 4(M) x 4(N); warp tile 32 x 64

    float acc[2][8][4];
#pragma unroll
    for (int i = 0; i < 2; i++)
#pragma unroll
        for (int j = 0; j < 8; j++)
#pragma unroll
            for (int k = 0; k < 4; k++) acc[i][j][k] = 0.f;

    load_chunk(0, sb, t, m0);
    load_chunk(1, sb + STG_SZ, t, m0);

    // A-side geometry from R4/R5 passing kernel (warp m-tile 32, mf 0..1)
    const uint32_t arow  = (uint32_t)(wm * 32 + (lane & 15));
    const uint32_t acol8 = (uint32_t)(lane >> 4);
    // B-side geometry from R11-R13 passing kernel (warp n-tile 64, nf2 0..3)
    const uint32_t brow  = (uint32_t)(wn * 64 + (lane & 7) + ((lane >> 4) & 1) * 8);
    const uint32_t bcol8 = (uint32_t)((lane >> 3) & 1);

#pragma unroll 1
    for (int c = 0; c < NCHUNK; c++) {
        const uint32_t stg = sb + (uint32_t)(c % NSTAGE) * STG_SZ;

        asm volatile("cp.async.wait_group 1;" ::: "memory");
        __syncthreads();

        if (c + 2 < NCHUNK)
            load_chunk(c + 2, sb + (uint32_t)((c + 2) % NSTAGE) * STG_SZ, t, m0);

#pragma unroll
        for (int ks = 0; ks < 4; ks++) {
            uint32_t av[2][4];
#pragma unroll
            for (int mf = 0; mf < 2; mf++) {
                uint32_t off = sw128((arow + mf * 16) * 128 + (ks * 16 + acol8 * 8) * 2);
                ldm4(av[mf], stg + O_A + off);
            }
#pragma unroll
            for (int nf2 = 0; nf2 < 4; nf2++) {
                uint32_t bv[4];
                uint32_t off = sw128((brow + nf2 * 16) * 128 + (ks * 16 + bcol8 * 8) * 2);
                ldm4(bv, stg + O_B + off);
#pragma unroll
                for (int mf = 0; mf < 2; mf++)
#pragma unroll
                    for (int j = 0; j < 2; j++)
                        mma_f16(acc[mf][nf2 * 2 + j], av[mf], &bv[2 * j]);
            }
        }
    }

    const int gid = lane >> 2, t4 = lane & 3;
    float2 bb0[8], bb1[8], bb2[8];
#pragma unroll
    for (int nf = 0; nf < 8; nf++) {
        int col = wn * 64 + nf * 8 + t4 * 2;
        bb0[nf] = *reinterpret_cast<const float2*>(b0 + col);
        bb1[nf] = *reinterpret_cast<const float2*>(b1 + col);
        bb2[nf] = *reinterpret_cast<const float2*>(b2 + col);
    }
#pragma unroll
    for (int mf = 0; mf < 2; mf++) {
#pragma unroll
        for (int half = 0; half < 2; half++) {
            int row = m0 + wm * 32 + mf * 16 + gid + half * 8;
            if (row >= NN) continue;
            float f0 = g_flg[row], f1 = g_flg[NN + row], f2 = g_flg[2 * NN + row];
#pragma unroll
            for (int nf = 0; nf < 8; nf++) {
                int col = wn * 64 + nf * 8 + t4 * 2;
                float2 o;
                o.x = fmaxf(acc[mf][nf][2 * half]     + f0 * bb0[nf].x + f1 * bb1[nf].x + f2 * bb2[nf].x, 0.f);
                o.y = fmaxf(acc[mf][nf][2 * half + 1] + f0 * bb0[nf].y + f1 * bb1[nf].y + f2 * bb2[nf].y, 0.f);
                *reinterpret_cast<float2*>(out + (size_t)row * DD + col) = o;
            }
        }
    }
}

// ================= launch =================
extern "C" void kernel_launch(void* const* d_in, const int* in_sizes, int n_in,
                              void* d_out, int out_size)
{
    const float* features = (const float*)d_in[0];
    const void*  src0 = d_in[1]; const void* dst0 = d_in[2];
    const void*  src1 = d_in[3]; const void* dst1 = d_in[4];
    const void*  src2 = d_in[5]; const void* dst2 = d_in[6];
    const float* W0 = (const float*)d_in[7];  const float* b0 = (const float*)d_in[8];
    const float* W1 = (const float*)d_in[9];  const float* b1 = (const float*)d_in[10];
    const float* W2 = (const float*)d_in[11]; const float* b2 = (const float*)d_in[12];
    float* out = (float*)d_out;

    cudaFuncSetAttribute(gemm_mma_kernel, cudaFuncAttributeMaxDynamicSharedMemorySize,
                         SMEM_GEMM);

    init_kernel<<<ZB + FB + BB, 256>>>((const int*)src0, features, W0, W1, W2);
    {
        dim3 grid((EE + 255) / 256, 1, 3);
        bucket_kernel<<<grid, 256>>>(src0, dst0, src1, dst1, src2, dst2);
    }
    {
        int blocks = (NSEG3 * 32 + 255) / 256;
        node_gather_kernel<<<blocks, 256>>>();
    }
    {
        dim3 grid(MPAD / 128, 1);
        gemm_mma_kernel<<<grid, GTHREADS, SMEM_GEMM>>>(b0, b1, b2, out);
    }
}